// round 12
// baseline (speedup 1.0000x reference)
#include <cuda_runtime.h>
#include <cuda_fp16.h>
#include <cstdint>

#define BATCH 64
#define SEQ   64
#define EMBED 1024
#define NHEAD 16
#define HDIM  64
#define VOCAB 50257
#define M_TOT (BATCH*SEQ)   /* 4096 */

#define N_PAD  50304        /* 393*128 */
#define K_EFF  2048         /* A sections for qkv/wo: [hi | lo] fp16 */
#define KB_DIM 1024         /* B single fp16 section; also wu A (y-hi) stride */
#define NK_QKV 32           /* K_EFF / 64 */
#define NK_WU  16           /* KB_DIM / 64 */

// ---------------- scratch (no allocation allowed) ----------------
__device__ float g_emb[M_TOT*EMBED];
__device__ float g_q  [M_TOT*EMBED];
__device__ float g_k  [M_TOT*EMBED];
__device__ float g_v  [M_TOT*EMBED];
// fp16 operands (K-major)
__device__ __align__(16) __half g_A2  [(size_t)M_TOT * K_EFF];    // [hi|lo]: emb-split, then cat-split
__device__ __align__(16) __half g_A3  [(size_t)M_TOT * KB_DIM];   // y-hi only
__device__ __align__(16) __half g_Bqkv[(size_t)3072  * KB_DIM];   // [Wq|Wk|Wv]
__device__ __align__(16) __half g_Bwo [(size_t)EMBED * KB_DIM];   // Wo
__device__ __align__(16) __half g_B2  [(size_t)N_PAD * KB_DIM];   // Wu

// ---------------- helpers ----------------
__device__ __forceinline__ uint32_t smem_u32(const void* p) {
    uint32_t a;
    asm("{ .reg .u64 t; cvta.to.shared.u64 t, %1; cvt.u32.u64 %0, t; }" : "=r"(a) : "l"(p));
    return a;
}
__device__ __forceinline__ void cp16(uint32_t dst, const void* src) {
    asm volatile("cp.async.cg.shared.global [%0], [%1], 16;" :: "r"(dst), "l"(src) : "memory");
}
#define CP_COMMIT() asm volatile("cp.async.commit_group;" ::: "memory")
#define CP_WAIT(N)  asm volatile("cp.async.wait_group %0;" :: "n"(N) : "memory")

__device__ __forceinline__ void ldm_x4(uint32_t (&r)[4], uint32_t addr) {
    asm volatile("ldmatrix.sync.aligned.m8n8.x4.shared.b16 {%0,%1,%2,%3}, [%4];"
        : "=r"(r[0]), "=r"(r[1]), "=r"(r[2]), "=r"(r[3]) : "r"(addr));
}
__device__ __forceinline__ void mma_f16(float (&d)[4], const uint32_t (&a)[4],
                                        uint32_t b0, uint32_t b1) {
    asm volatile("mma.sync.aligned.m16n8k16.row.col.f32.f16.f16.f32 "
        "{%0,%1,%2,%3}, {%4,%5,%6,%7}, {%8,%9}, {%0,%1,%2,%3};"
        : "+f"(d[0]), "+f"(d[1]), "+f"(d[2]), "+f"(d[3])
        : "r"(a[0]), "r"(a[1]), "r"(a[2]), "r"(a[3]), "r"(b0), "r"(b1));
}
__device__ __forceinline__ __half2 split_hi2(float a, float b, __half2& lo) {
    __half ha = __float2half_rn(a);
    __half hb = __float2half_rn(b);
    lo = __half2(__float2half_rn(a - __half2float(ha)),
                 __float2half_rn(b - __half2float(hb)));
    return __half2(ha, hb);
}

// ================= 128x128 HMMA mainloop (qkv / wo) =================
// k-chunk 64 per stage, 3-stage cp.async ring.
// Stage layout (32KB): A [2 sub][128 rows][32 fp16 (64B, XOR swizzled)], B same at +16KB.
#define STG_SZ 32768

__device__ __forceinline__ void fill_stage(uint32_t sbase, const __half* Ab, int strideA,
                                           const __half* Bb, int kt, int tid)
{
    const int ka = kt * 64;
    const int kb = (kt & 15) * 64;
    #pragma unroll
    for (int i = 0; i < 4; i++) {
        int c = tid + i * 256;                 // 0..1023
        int row = c >> 3, ck = c & 7;
        uint32_t off = (ck >> 2) * 8192 + row * 64 + (((ck & 3) ^ ((row >> 1) & 3)) << 4);
        cp16(sbase + off, Ab + (size_t)row * strideA + ka + ck * 8);
    }
    #pragma unroll
    for (int i = 0; i < 4; i++) {
        int c = tid + i * 256;
        int row = c >> 3, ck = c & 7;
        uint32_t off = 16384 + (ck >> 2) * 8192 + row * 64 + (((ck & 3) ^ ((row >> 1) & 3)) << 4);
        cp16(sbase + off, Bb + (size_t)row * KB_DIM + kb + ck * 8);
    }
}

__device__ __forceinline__ void compute_stage(uint32_t sbase, float (&acc)[4][4][4],
                                              int lane, int wm, int wn)
{
    const int a_r8 = (lane & 7) + ((lane >> 3) & 1) * 8;
    const int a_kh = (lane >> 4) * 8;
    const int b_r8 = (lane & 7) + (lane >> 4) * 8;
    const int b_kh = ((lane >> 3) & 1) * 8;
    #pragma unroll
    for (int sub = 0; sub < 2; sub++) {
        const uint32_t A0 = sbase + sub * 8192;
        const uint32_t B0 = sbase + 16384 + sub * 8192;
        #pragma unroll
        for (int ks = 0; ks < 32; ks += 16) {
            uint32_t af[4][4], bf[4][2];
            #pragma unroll
            for (int mi = 0; mi < 4; mi++) {
                int row = wm + mi * 16 + a_r8;
                int kk  = ks + a_kh;
                ldm_x4(af[mi], A0 + row * 64 + (((kk >> 3) ^ ((row >> 1) & 3)) << 4));
            }
            #pragma unroll
            for (int nj = 0; nj < 2; nj++) {
                int row = wn + nj * 16 + b_r8;
                int kk  = ks + b_kh;
                uint32_t t[4];
                ldm_x4(t, B0 + row * 64 + (((kk >> 3) ^ ((row >> 1) & 3)) << 4));
                bf[nj * 2][0]     = t[0]; bf[nj * 2][1]     = t[1];
                bf[nj * 2 + 1][0] = t[2]; bf[nj * 2 + 1][1] = t[3];
            }
            #pragma unroll
            for (int mi = 0; mi < 4; mi++)
                #pragma unroll
                for (int nj = 0; nj < 4; nj++)
                    mma_f16(acc[mi][nj], af[mi], bf[nj][0], bf[nj][1]);
        }
    }
}

__device__ __forceinline__ void hmma_loop(const __half* Ab, int strideA,
                                          const __half* Bb, int nk,
                                          char* sm, float (&acc)[4][4][4],
                                          int tid, int lane, int wm, int wn)
{
    #pragma unroll
    for (int i = 0; i < 4; i++)
        #pragma unroll
        for (int j = 0; j < 4; j++)
            #pragma unroll
            for (int r = 0; r < 4; r++) acc[i][j][r] = 0.f;

    const uint32_t sb = smem_u32(sm);
    fill_stage(sb,          Ab, strideA, Bb, 0, tid); CP_COMMIT();
    fill_stage(sb + STG_SZ, Ab, strideA, Bb, 1, tid); CP_COMMIT();

    for (int kt = 0; kt < nk; kt++) {
        CP_WAIT(1);
        __syncthreads();
        if (kt + 2 < nk)
            fill_stage(sb + ((kt + 2) % 3) * STG_SZ, Ab, strideA, Bb, kt + 2, tid);
        CP_COMMIT();
        compute_stage(sb + (kt % 3) * STG_SZ, acc, lane, wm, wn);
    }
}

// ================= 256x128 HMMA mainloop (wu) =================
// Stage (48KB): A [2 sub][256 rows][32 fp16], B [2 sub][128 rows][32 fp16] at +32KB.
#define STG2_SZ 49152

__device__ __forceinline__ void fill_stage256(uint32_t sbase, const __half* Ab,
                                              const __half* Bb, int kt, int tid)
{
    const int ka = kt * 64;
    const int kb = (kt & 15) * 64;
    #pragma unroll
    for (int i = 0; i < 8; i++) {
        int c = tid + i * 256;                 // 0..2047
        int row = c >> 3, ck = c & 7;
        uint32_t off = (ck >> 2) * 16384 + row * 64 + (((ck & 3) ^ ((row >> 1) & 3)) << 4);
        cp16(sbase + off, Ab + (size_t)row * KB_DIM + ka + ck * 8);
    }
    #pragma unroll
    for (int i = 0; i < 4; i++) {
        int c = tid + i * 256;                 // 0..1023
        int row = c >> 3, ck = c & 7;
        uint32_t off = 32768 + (ck >> 2) * 8192 + row * 64 + (((ck & 3) ^ ((row >> 1) & 3)) << 4);
        cp16(sbase + off, Bb + (size_t)row * KB_DIM + kb + ck * 8);
    }
}

__device__ __forceinline__ void compute_stage256(uint32_t sbase, float (&acc)[4][8][4],
                                                 int lane, int wm, int wn)
{
    const int a_r8 = (lane & 7) + ((lane >> 3) & 1) * 8;
    const int a_kh = (lane >> 4) * 8;
    const int b_r8 = (lane & 7) + (lane >> 4) * 8;
    const int b_kh = ((lane >> 3) & 1) * 8;
    #pragma unroll
    for (int sub = 0; sub < 2; sub++) {
        const uint32_t A0 = sbase + sub * 16384;
        const uint32_t B0 = sbase + 32768 + sub * 8192;
        #pragma unroll
        for (int ks = 0; ks < 32; ks += 16) {
            uint32_t af[4][4], bf[8][2];
            #pragma unroll
            for (int mi = 0; mi < 4; mi++) {
                int row = wm + mi * 16 + a_r8;
                int kk  = ks + a_kh;
                ldm_x4(af[mi], A0 + row * 64 + (((kk >> 3) ^ ((row >> 1) & 3)) << 4));
            }
            #pragma unroll
            for (int njj = 0; njj < 4; njj++) {
                int row = wn + njj * 16 + b_r8;
                int kk  = ks + b_kh;
                uint32_t t[4];
                ldm_x4(t, B0 + row * 64 + (((kk >> 3) ^ ((row >> 1) & 3)) << 4));
                bf[njj * 2][0]     = t[0]; bf[njj * 2][1]     = t[1];
                bf[njj * 2 + 1][0] = t[2]; bf[njj * 2 + 1][1] = t[3];
            }
            #pragma unroll
            for (int mi = 0; mi < 4; mi++)
                #pragma unroll
                for (int nj = 0; nj < 8; nj++)
                    mma_f16(acc[mi][nj], af[mi], bf[nj][0], bf[nj][1]);
        }
    }
}

// ---------------- embed (+ fused emb-split into g_A2) ----------------
__global__ void __launch_bounds__(256) embed_kernel(const int* __restrict__ x,
                                                    const float* __restrict__ E,
                                                    const float* __restrict__ pe)
{
    int idx = blockIdx.x * 256 + threadIdx.x;
    int row = idx >> 8;
    int c   = (idx & 255) << 2;
    int tok = x[row];
    float4 e = *(const float4*)(E  + (size_t)tok * EMBED + c);
    float4 p = *(const float4*)(pe + (size_t)(row & 63) * EMBED + c);
    e.x += p.x; e.y += p.y; e.z += p.z; e.w += p.w;
    *(float4*)(g_emb + (size_t)row * EMBED + c) = e;

    __half2 l01, l23;
    __half2 h01 = split_hi2(e.x, e.y, l01);
    __half2 h23 = split_hi2(e.z, e.w, l23);
    size_t base = (size_t)row * K_EFF;
    *(__half2*)(g_A2 + base + c)            = h01;
    *(__half2*)(g_A2 + base + c + 2)        = h23;
    *(__half2*)(g_A2 + base + 1024 + c)     = l01;
    *(__half2*)(g_A2 + base + 1024 + c + 2) = l23;
}

// ---------------- weight prepasses (single fp16 section, K-major) ----------------
__global__ void __launch_bounds__(256) conv_w_qkv(const float* __restrict__ Wq,
                                                  const float* __restrict__ Wk,
                                                  const float* __restrict__ Wv)
{
    __shared__ float t[32][33];
    const float* W = (blockIdx.z == 0) ? Wq : (blockIdx.z == 1) ? Wk : Wv;
    int n0 = blockIdx.x * 32;
    int k0 = blockIdx.y * 32;
    int tx = threadIdx.x, ty = threadIdx.y;   // 32 x 8
    int h  = n0 >> 6, e0 = n0 & 63;
    #pragma unroll
    for (int i = 0; i < 4; i++) {
        int kk = ty + i * 8;
        t[kk][tx] = W[(size_t)h * (EMBED * HDIM) + (size_t)(k0 + kk) * HDIM + e0 + tx];
    }
    __syncthreads();
    #pragma unroll
    for (int i = 0; i < 4; i++) {
        int nn = ty + i * 8;
        int k  = k0 + tx;
        g_Bqkv[(size_t)(blockIdx.z * 1024 + n0 + nn) * KB_DIM + k] =
            __float2half_rn(t[tx][nn]);
    }
}

__global__ void __launch_bounds__(256) conv_w_o(const float* __restrict__ Wo)
{
    __shared__ float t[32][33];
    int n0 = blockIdx.x * 32;
    int k0 = blockIdx.y * 32;
    int tx = threadIdx.x, ty = threadIdx.y;
    #pragma unroll
    for (int i = 0; i < 4; i++) {
        int kk = ty + i * 8;
        t[kk][tx] = Wo[(size_t)(k0 + kk) * EMBED + n0 + tx];
    }
    __syncthreads();
    #pragma unroll
    for (int i = 0; i < 4; i++) {
        int nn = ty + i * 8;
        int k  = k0 + tx;
        g_Bwo[(size_t)(n0 + nn) * KB_DIM + k] = __float2half_rn(t[tx][nn]);
    }
}

// Wu: [1024 k][VOCAB n] (odd stride -> scalar loads) -> g_B2[n][k]
__global__ void __launch_bounds__(256) conv_wu_kernel(const float* __restrict__ Wu)
{
    __shared__ float t[32][33];
    int n0 = blockIdx.x * 32;
    int k0 = blockIdx.y * 32;
    int tx = threadIdx.x, ty = threadIdx.y;
    #pragma unroll
    for (int i = 0; i < 4; i++) {
        int k = k0 + ty + i * 8;
        int n = n0 + tx;
        t[ty + i * 8][tx] = (n < VOCAB) ? Wu[(size_t)k * VOCAB + n] : 0.f;
    }
    __syncthreads();
    #pragma unroll
    for (int i = 0; i < 4; i++) {
        int n = n0 + ty + i * 8;
        int k = k0 + tx;
        g_B2[(size_t)n * KB_DIM + k] = __float2half_rn(t[tx][ty + i * 8]);
    }
}

// ---------------- attention (fp32) + fused cat-split into g_A2 ----------------
__global__ void __launch_bounds__(256) attn_kernel()
{
    __shared__ float sQ [64][68];
    __shared__ float sKV[64][68];
    int bh  = blockIdx.x;
    int tid = threadIdx.x;
    const float* qb = g_q + (size_t)bh * (SEQ * HDIM);
    const float* kb = g_k + (size_t)bh * (SEQ * HDIM);
    const float* vb = g_v + (size_t)bh * (SEQ * HDIM);
    #pragma unroll
    for (int i = 0; i < 4; i++) {
        int idx = tid + i * 256;
        int r = idx >> 4, c = (idx & 15) << 2;
        *(float4*)(&sQ [r][c]) = *(const float4*)(qb + r * 64 + c);
        *(float4*)(&sKV[r][c]) = *(const float4*)(kb + r * 64 + c);
    }
    __syncthreads();

    int s = tid >> 2, q = tid & 3;
    float4 qv[16];
    #pragma unroll
    for (int k4 = 0; k4 < 16; k4++) qv[k4] = *(const float4*)(&sQ[s][k4 * 4]);

    float sc[16];
    #pragma unroll
    for (int j = 0; j < 16; j++) {
        int t = q + 4 * j;
        float d = 0.f;
        #pragma unroll
        for (int k4 = 0; k4 < 16; k4++) {
            float4 kv = *(const float4*)(&sKV[t][k4 * 4]);
            d += qv[k4].x * kv.x + qv[k4].y * kv.y + qv[k4].z * kv.z + qv[k4].w * kv.w;
        }
        sc[j] = (t <= s) ? d * 0.125f : -1e30f;
    }
    float mx = sc[0];
    #pragma unroll
    for (int j = 1; j < 16; j++) mx = fmaxf(mx, sc[j]);
    mx = fmaxf(mx, __shfl_xor_sync(0xFFFFFFFFu, mx, 1));
    mx = fmaxf(mx, __shfl_xor_sync(0xFFFFFFFFu, mx, 2));
    float sum = 0.f;
    #pragma unroll
    for (int j = 0; j < 16; j++) { sc[j] = __expf(sc[j] - mx); sum += sc[j]; }
    sum += __shfl_xor_sync(0xFFFFFFFFu, sum, 1);
    sum += __shfl_xor_sync(0xFFFFFFFFu, sum, 2);
    float inv = 1.f / sum;
    #pragma unroll
    for (int j = 0; j < 16; j++) sc[j] *= inv;

    __syncthreads();
    #pragma unroll
    for (int i = 0; i < 4; i++) {
        int idx = tid + i * 256;
        int r = idx >> 4, c = (idx & 15) << 2;
        *(float4*)(&sKV[r][c]) = *(const float4*)(vb + r * 64 + c);
    }
    __syncthreads();

    float po[64];
    #pragma unroll
    for (int e = 0; e < 64; e++) po[e] = 0.f;
    #pragma unroll
    for (int j = 0; j < 16; j++) {
        int t = q + 4 * j;
        float w = sc[j];
        #pragma unroll
        for (int e4 = 0; e4 < 16; e4++) {
            float4 v = *(const float4*)(&sKV[t][e4 * 4]);
            po[e4 * 4 + 0] += w * v.x;
            po[e4 * 4 + 1] += w * v.y;
            po[e4 * 4 + 2] += w * v.z;
            po[e4 * 4 + 3] += w * v.w;
        }
    }
    #pragma unroll
    for (int e = 0; e < 64; e++) {
        po[e] += __shfl_xor_sync(0xFFFFFFFFu, po[e], 1);
        po[e] += __shfl_xor_sync(0xFFFFFFFFu, po[e], 2);
    }
    // fused cat-split: this thread owns row (b,s), cols h*64 + [16q, 16q+16)
    int b = bh >> 4, h = bh & 15;
    int row = b * SEQ + s;
    size_t base = (size_t)row * K_EFF + h * HDIM + q * 16;
    #pragma unroll
    for (int i = 0; i < 8; i++) {
        int e0 = q * 16 + i * 2;
        __half2 lo;
        __half2 hi = split_hi2(po[e0], po[e0 + 1], lo);
        *(__half2*)(g_A2 + base + i * 2)        = hi;
        *(__half2*)(g_A2 + base + 1024 + i * 2) = lo;
    }
}

// ---------------- QKV on HMMA: [emb-split] @ fp16([Wq|Wk|Wv]) ----------------
__global__ void __launch_bounds__(256, 2) qkv_mma(const float* __restrict__ bq,
                                                  const float* __restrict__ bk,
                                                  const float* __restrict__ bv)
{
    extern __shared__ char sm[];
    const int tid = threadIdx.x, lane = tid & 31, wid = tid >> 5;
    const int wm = (wid & 1) * 64, wn = (wid >> 1) * 32;
    const int m0 = blockIdx.x * 128;
    const int n0 = blockIdx.y * 128;     // global n in [0, 3072)

    float acc[4][4][4];
    hmma_loop(g_A2 + (size_t)m0 * K_EFF, K_EFF,
              g_Bqkv + (size_t)n0 * KB_DIM, NK_QKV,
              sm, acc, tid, lane, wm, wn);

    const int which = n0 >> 10;          // uniform per CTA
    float* outp = (which == 0) ? g_q : (which == 1) ? g_k : g_v;
    const float* bias = (which == 0) ? bq : (which == 1) ? bk : bv;

    const int er = lane >> 2;
    const int ec = (lane & 3) * 2;
    #pragma unroll
    for (int mi = 0; mi < 4; mi++) {
        #pragma unroll
        for (int nj = 0; nj < 4; nj++) {
            int col = n0 + wn + nj * 8 + ec;      // global
            int n   = col & 1023;                  // within weight
            int h = n >> 6, e = n & 63;
            float b0v = bias[n], b1v = bias[n + 1];
            int row0 = m0 + wm + mi * 16 + er;
            #pragma unroll
            for (int half = 0; half < 2; half++) {
                int row = row0 + half * 8;
                int b = row >> 6, s = row & 63;
                float* dst = outp + (size_t)(((b * NHEAD + h) * SEQ + s) * HDIM + e);
                *(float2*)dst = make_float2(acc[mi][nj][half * 2] + b0v,
                                            acc[mi][nj][half * 2 + 1] + b1v);
            }
        }
    }
}

// ---------------- Wo on HMMA: y = cat-split @ fp16(Wo) + bo + emb; emit fp16(y) ----------------
__global__ void __launch_bounds__(256, 2) wo_mma(const float* __restrict__ bo)
{
    extern __shared__ char sm[];
    const int tid = threadIdx.x, lane = tid & 31, wid = tid >> 5;
    const int wm = (wid & 1) * 64, wn = (wid >> 1) * 32;
    const int m0 = blockIdx.x * 128;
    const int n0 = blockIdx.y * 128;

    float acc[4][4][4];
    hmma_loop(g_A2 + (size_t)m0 * K_EFF, K_EFF,
              g_Bwo + (size_t)n0 * KB_DIM, NK_QKV,
              sm, acc, tid, lane, wm, wn);

    const int er = lane >> 2;
    const int ec = (lane & 3) * 2;
    #pragma unroll
    for (int mi = 0; mi < 4; mi++) {
        #pragma unroll
        for (int nj = 0; nj < 4; nj++) {
            int col = n0 + wn + nj * 8 + ec;
            float b0v = bo[col], b1v = bo[col + 1];
            int row0 = m0 + wm + mi * 16 + er;
            #pragma unroll
            for (int half = 0; half < 2; half++) {
                int row = row0 + half * 8;
                float2 em = *(const float2*)(g_emb + (size_t)row * EMBED + col);
                float y0 = acc[mi][nj][half * 2]     + b0v + em.x;
                float y1 = acc[mi][nj][half * 2 + 1] + b1v + em.y;
                *(__half2*)(g_A3 + (size_t)row * KB_DIM + col) =
                    __half2(__float2half_rn(y0), __float2half_rn(y1));
            }
        }
    }
}

// ---------------- logits on HMMA 256x128: out = fp16(y) @ fp16(Wu) + bu ----------------
// out rows have odd stride (VOCAB) -> scalar stores only.
__global__ void __launch_bounds__(256, 1) wu_mma(const float* __restrict__ bu,
                                                 float* __restrict__ out)
{
    extern __shared__ char sm[];
    const int tid = threadIdx.x, lane = tid & 31, wid = tid >> 5;
    const int wm = (wid & 3) * 64, wn = (wid >> 2) * 64;
    const int m0 = blockIdx.x * 256;
    const int n0 = blockIdx.y * 128;

    float acc[4][8][4];
    #pragma unroll
    for (int i = 0; i < 4; i++)
        #pragma unroll
        for (int j = 0; j < 8; j++)
            #pragma unroll
            for (int r = 0; r < 4; r++) acc[i][j][r] = 0.f;

    const __half* Ab = g_A3 + (size_t)m0 * KB_DIM;
    const __half* Bb = g_B2 + (size_t)n0 * KB_DIM;
    const uint32_t sb = smem_u32(sm);
    fill_stage256(sb,           Ab, Bb, 0, tid); CP_COMMIT();
    fill_stage256(sb + STG2_SZ, Ab, Bb, 1, tid); CP_COMMIT();

    for (int kt = 0; kt < NK_WU; kt++) {
        CP_WAIT(1);
        __syncthreads();
        if (kt + 2 < NK_WU)
            fill_stage256(sb + ((kt + 2) % 3) * STG2_SZ, Ab, Bb, kt + 2, tid);
        CP_COMMIT();
        compute_stage256(sb + (kt % 3) * STG2_SZ, acc, lane, wm, wn);
    }

    const int er = lane >> 2;
    const int ec = (lane & 3) * 2;
    #pragma unroll
    for (int mi = 0; mi < 4; mi++) {
        #pragma unroll
        for (int nj = 0; nj < 8; nj++) {
            int col = n0 + wn + nj * 8 + ec;
            float b0v = (col < VOCAB)     ? __ldg(bu + col)     : 0.f;
            float b1v = (col + 1 < VOCAB) ? __ldg(bu + col + 1) : 0.f;
            int row = m0 + wm + mi * 16 + er;
            float* p0 = out + (size_t)row * VOCAB + col;
            float* p1 = out + (size_t)(row + 8) * VOCAB + col;
            if (col < VOCAB) {
                p0[0] = acc[mi][nj][0] + b0v;
                p1[0] = acc[mi][nj][2] + b0v;
            }
            if (col + 1 < VOCAB) {
                p0[1] = acc[mi][nj][1] + b1v;
                p1[1] = acc[mi][nj][3] + b1v;
            }
        }
    }
}

// ---------------- launch ----------------
#define MMA_SMEM  (3 * STG_SZ)    /* 98304 */
#define MMA2_SMEM (3 * STG2_SZ)   /* 147456 */

extern "C" void kernel_launch(void* const* d_in, const int* in_sizes, int n_in,
                              void* d_out, int out_size)
{
    const int*   x  = (const int*)  d_in[0];
    const float* E  = (const float*)d_in[1];
    const float* pe = (const float*)d_in[2];
    const float* Wq = (const float*)d_in[3];
    const float* bq = (const float*)d_in[4];
    const float* Wk = (const float*)d_in[5];
    const float* bk = (const float*)d_in[6];
    const float* Wv = (const float*)d_in[7];
    const float* bv = (const float*)d_in[8];
    const float* Wo = (const float*)d_in[9];
    const float* bo = (const float*)d_in[10];
    const float* Wu = (const float*)d_in[11];
    const float* bu = (const float*)d_in[12];
    float* out = (float*)d_out;

    cudaFuncSetAttribute(qkv_mma, cudaFuncAttributeMaxDynamicSharedMemorySize, MMA_SMEM);
    cudaFuncSetAttribute(wo_mma,  cudaFuncAttributeMaxDynamicSharedMemorySize, MMA_SMEM);
    cudaFuncSetAttribute(wu_mma,  cudaFuncAttributeMaxDynamicSharedMemorySize, MMA2_SMEM);

    embed_kernel<<<4096, 256>>>(x, E, pe);                              // emb + emb-split
    conv_w_qkv<<<dim3(32, 32, 3), dim3(32, 8)>>>(Wq, Wk, Wv);           // weight fp16
    conv_w_o  <<<dim3(32, 32),    dim3(32, 8)>>>(Wo);
    conv_wu_kernel<<<dim3(N_PAD / 32, EMBED / 32), dim3(32, 8)>>>(Wu);

    qkv_mma<<<dim3(32, 24), 256, MMA_SMEM>>>(bq, bk, bv);               // q,k,v

    attn_kernel<<<BATCH * NHEAD, 256>>>();                              // -> cat-split in g_A2

    wo_mma<<<dim3(32, 8), 256, MMA_SMEM>>>(bo);                         // y-hi -> g_A3

    wu_mma<<<dim3(16, N_PAD / 128), 256, MMA2_SMEM>>>(bu, out);         // logits
}

// round 13
// speedup vs baseline: 1.1186x; 1.1186x over previous
#include <cuda_runtime.h>
#include <cuda_fp16.h>
#include <cstdint>

#define BATCH 64
#define SEQ   64
#define EMBED 1024
#define NHEAD 16
#define HDIM  64
#define VOCAB 50257
#define M_TOT (BATCH*SEQ)   /* 4096 */

#define N_PAD  50304        /* 393*128 */
#define K_EFF  2048         /* A sections for qkv/wo: [hi | lo] fp16 */
#define KB_DIM 1024         /* B single fp16 section; also wu A (y-hi) stride */
#define NK_QKV 32           /* K_EFF / 64 */
#define NK_WU  16           /* KB_DIM / 64 */

// ---------------- scratch (no allocation allowed) ----------------
__device__ float g_emb[M_TOT*EMBED];
__device__ float g_q  [M_TOT*EMBED];
__device__ float g_k  [M_TOT*EMBED];
__device__ float g_v  [M_TOT*EMBED];
// fp16 operands (K-major)
__device__ __align__(16) __half g_A2  [(size_t)M_TOT * K_EFF];    // [hi|lo]: emb-split, then cat-split
__device__ __align__(16) __half g_A3  [(size_t)M_TOT * KB_DIM];   // y-hi only
__device__ __align__(16) __half g_Bqkv[(size_t)3072  * KB_DIM];   // [Wq|Wk|Wv]
__device__ __align__(16) __half g_Bwo [(size_t)EMBED * KB_DIM];   // Wo
__device__ __align__(16) __half g_B2  [(size_t)N_PAD * KB_DIM];   // Wu

// ---------------- helpers ----------------
__device__ __forceinline__ uint32_t smem_u32(const void* p) {
    uint32_t a;
    asm("{ .reg .u64 t; cvta.to.shared.u64 t, %1; cvt.u32.u64 %0, t; }" : "=r"(a) : "l"(p));
    return a;
}
__device__ __forceinline__ void cp16(uint32_t dst, const void* src) {
    asm volatile("cp.async.cg.shared.global [%0], [%1], 16;" :: "r"(dst), "l"(src) : "memory");
}
#define CP_COMMIT() asm volatile("cp.async.commit_group;" ::: "memory")
#define CP_WAIT(N)  asm volatile("cp.async.wait_group %0;" :: "n"(N) : "memory")

__device__ __forceinline__ void ldm_x4(uint32_t (&r)[4], uint32_t addr) {
    asm volatile("ldmatrix.sync.aligned.m8n8.x4.shared.b16 {%0,%1,%2,%3}, [%4];"
        : "=r"(r[0]), "=r"(r[1]), "=r"(r[2]), "=r"(r[3]) : "r"(addr));
}
__device__ __forceinline__ void mma_f16(float (&d)[4], const uint32_t (&a)[4],
                                        uint32_t b0, uint32_t b1) {
    asm volatile("mma.sync.aligned.m16n8k16.row.col.f32.f16.f16.f32 "
        "{%0,%1,%2,%3}, {%4,%5,%6,%7}, {%8,%9}, {%0,%1,%2,%3};"
        : "+f"(d[0]), "+f"(d[1]), "+f"(d[2]), "+f"(d[3])
        : "r"(a[0]), "r"(a[1]), "r"(a[2]), "r"(a[3]), "r"(b0), "r"(b1));
}
__device__ __forceinline__ __half2 split_hi2(float a, float b, __half2& lo) {
    __half ha = __float2half_rn(a);
    __half hb = __float2half_rn(b);
    lo = __half2(__float2half_rn(a - __half2float(ha)),
                 __float2half_rn(b - __half2float(hb)));
    return __half2(ha, hb);
}

// ================= 128x128 HMMA mainloop (all GEMMs) =================
// k-chunk 64 per stage, 3-stage cp.async ring, 2 CTAs/SM.
// Stage layout (32KB): A [2 sub][128 rows][32 fp16 (64B, XOR swizzled)], B same at +16KB.
#define STG_SZ 32768

__device__ __forceinline__ void fill_stage(uint32_t sbase, const __half* Ab, int strideA,
                                           const __half* Bb, int kt, int tid)
{
    const int ka = kt * 64;
    const int kb = (kt & 15) * 64;
    #pragma unroll
    for (int i = 0; i < 4; i++) {
        int c = tid + i * 256;                 // 0..1023
        int row = c >> 3, ck = c & 7;
        uint32_t off = (ck >> 2) * 8192 + row * 64 + (((ck & 3) ^ ((row >> 1) & 3)) << 4);
        cp16(sbase + off, Ab + (size_t)row * strideA + ka + ck * 8);
    }
    #pragma unroll
    for (int i = 0; i < 4; i++) {
        int c = tid + i * 256;
        int row = c >> 3, ck = c & 7;
        uint32_t off = 16384 + (ck >> 2) * 8192 + row * 64 + (((ck & 3) ^ ((row >> 1) & 3)) << 4);
        cp16(sbase + off, Bb + (size_t)row * KB_DIM + kb + ck * 8);
    }
}

__device__ __forceinline__ void compute_stage(uint32_t sbase, float (&acc)[4][4][4],
                                              int lane, int wm, int wn)
{
    const int a_r8 = (lane & 7) + ((lane >> 3) & 1) * 8;
    const int a_kh = (lane >> 4) * 8;
    const int b_r8 = (lane & 7) + (lane >> 4) * 8;
    const int b_kh = ((lane >> 3) & 1) * 8;
    #pragma unroll
    for (int sub = 0; sub < 2; sub++) {
        const uint32_t A0 = sbase + sub * 8192;
        const uint32_t B0 = sbase + 16384 + sub * 8192;
        #pragma unroll
        for (int ks = 0; ks < 32; ks += 16) {
            uint32_t af[4][4], bf[4][2];
            #pragma unroll
            for (int mi = 0; mi < 4; mi++) {
                int row = wm + mi * 16 + a_r8;
                int kk  = ks + a_kh;
                ldm_x4(af[mi], A0 + row * 64 + (((kk >> 3) ^ ((row >> 1) & 3)) << 4));
            }
            #pragma unroll
            for (int nj = 0; nj < 2; nj++) {
                int row = wn + nj * 16 + b_r8;
                int kk  = ks + b_kh;
                uint32_t t[4];
                ldm_x4(t, B0 + row * 64 + (((kk >> 3) ^ ((row >> 1) & 3)) << 4));
                bf[nj * 2][0]     = t[0]; bf[nj * 2][1]     = t[1];
                bf[nj * 2 + 1][0] = t[2]; bf[nj * 2 + 1][1] = t[3];
            }
            #pragma unroll
            for (int mi = 0; mi < 4; mi++)
                #pragma unroll
                for (int nj = 0; nj < 4; nj++)
                    mma_f16(acc[mi][nj], af[mi], bf[nj][0], bf[nj][1]);
        }
    }
}

__device__ __forceinline__ void hmma_loop(const __half* Ab, int strideA,
                                          const __half* Bb, int nk,
                                          char* sm, float (&acc)[4][4][4],
                                          int tid, int lane, int wm, int wn)
{
    #pragma unroll
    for (int i = 0; i < 4; i++)
        #pragma unroll
        for (int j = 0; j < 4; j++)
            #pragma unroll
            for (int r = 0; r < 4; r++) acc[i][j][r] = 0.f;

    const uint32_t sb = smem_u32(sm);
    fill_stage(sb,          Ab, strideA, Bb, 0, tid); CP_COMMIT();
    fill_stage(sb + STG_SZ, Ab, strideA, Bb, 1, tid); CP_COMMIT();

    for (int kt = 0; kt < nk; kt++) {
        CP_WAIT(1);                 // in-order completion: group kt is done
        __syncthreads();            // data visible; also guards ring reuse (WAR)
        if (kt + 2 < nk)
            fill_stage(sb + ((kt + 2) % 3) * STG_SZ, Ab, strideA, Bb, kt + 2, tid);
        CP_COMMIT();                // keep one group per iter (empty ok)
        compute_stage(sb + (kt % 3) * STG_SZ, acc, lane, wm, wn);
    }
}

// ---------------- embed (+ fused emb-split into g_A2) ----------------
__global__ void __launch_bounds__(256) embed_kernel(const int* __restrict__ x,
                                                    const float* __restrict__ E,
                                                    const float* __restrict__ pe)
{
    int idx = blockIdx.x * 256 + threadIdx.x;
    int row = idx >> 8;
    int c   = (idx & 255) << 2;
    int tok = x[row];
    float4 e = *(const float4*)(E  + (size_t)tok * EMBED + c);
    float4 p = *(const float4*)(pe + (size_t)(row & 63) * EMBED + c);
    e.x += p.x; e.y += p.y; e.z += p.z; e.w += p.w;
    *(float4*)(g_emb + (size_t)row * EMBED + c) = e;

    __half2 l01, l23;
    __half2 h01 = split_hi2(e.x, e.y, l01);
    __half2 h23 = split_hi2(e.z, e.w, l23);
    size_t base = (size_t)row * K_EFF;
    *(__half2*)(g_A2 + base + c)            = h01;
    *(__half2*)(g_A2 + base + c + 2)        = h23;
    *(__half2*)(g_A2 + base + 1024 + c)     = l01;
    *(__half2*)(g_A2 + base + 1024 + c + 2) = l23;
}

// ---------------- weight prepasses (single fp16 section, K-major) ----------------
__global__ void __launch_bounds__(256) conv_w_qkv(const float* __restrict__ Wq,
                                                  const float* __restrict__ Wk,
                                                  const float* __restrict__ Wv)
{
    __shared__ float t[32][33];
    const float* W = (blockIdx.z == 0) ? Wq : (blockIdx.z == 1) ? Wk : Wv;
    int n0 = blockIdx.x * 32;
    int k0 = blockIdx.y * 32;
    int tx = threadIdx.x, ty = threadIdx.y;   // 32 x 8
    int h  = n0 >> 6, e0 = n0 & 63;
    #pragma unroll
    for (int i = 0; i < 4; i++) {
        int kk = ty + i * 8;
        t[kk][tx] = W[(size_t)h * (EMBED * HDIM) + (size_t)(k0 + kk) * HDIM + e0 + tx];
    }
    __syncthreads();
    #pragma unroll
    for (int i = 0; i < 4; i++) {
        int nn = ty + i * 8;
        int k  = k0 + tx;
        g_Bqkv[(size_t)(blockIdx.z * 1024 + n0 + nn) * KB_DIM + k] =
            __float2half_rn(t[tx][nn]);
    }
}

__global__ void __launch_bounds__(256) conv_w_o(const float* __restrict__ Wo)
{
    __shared__ float t[32][33];
    int n0 = blockIdx.x * 32;
    int k0 = blockIdx.y * 32;
    int tx = threadIdx.x, ty = threadIdx.y;
    #pragma unroll
    for (int i = 0; i < 4; i++) {
        int kk = ty + i * 8;
        t[kk][tx] = Wo[(size_t)(k0 + kk) * EMBED + n0 + tx];
    }
    __syncthreads();
    #pragma unroll
    for (int i = 0; i < 4; i++) {
        int nn = ty + i * 8;
        int k  = k0 + tx;
        g_Bwo[(size_t)(n0 + nn) * KB_DIM + k] = __float2half_rn(t[tx][nn]);
    }
}

// Wu: [1024 k][VOCAB n] (odd stride -> scalar loads) -> g_B2[n][k]
__global__ void __launch_bounds__(256) conv_wu_kernel(const float* __restrict__ Wu)
{
    __shared__ float t[32][33];
    int n0 = blockIdx.x * 32;
    int k0 = blockIdx.y * 32;
    int tx = threadIdx.x, ty = threadIdx.y;
    #pragma unroll
    for (int i = 0; i < 4; i++) {
        int k = k0 + ty + i * 8;
        int n = n0 + tx;
        t[ty + i * 8][tx] = (n < VOCAB) ? Wu[(size_t)k * VOCAB + n] : 0.f;
    }
    __syncthreads();
    #pragma unroll
    for (int i = 0; i < 4; i++) {
        int n = n0 + ty + i * 8;
        int k = k0 + tx;
        g_B2[(size_t)n * KB_DIM + k] = __float2half_rn(t[tx][ty + i * 8]);
    }
}

// ---------------- attention (fp32) + fused cat-split into g_A2 ----------------
__global__ void __launch_bounds__(256) attn_kernel()
{
    __shared__ float sQ [64][68];
    __shared__ float sKV[64][68];
    int bh  = blockIdx.x;
    int tid = threadIdx.x;
    const float* qb = g_q + (size_t)bh * (SEQ * HDIM);
    const float* kb = g_k + (size_t)bh * (SEQ * HDIM);
    const float* vb = g_v + (size_t)bh * (SEQ * HDIM);
    #pragma unroll
    for (int i = 0; i < 4; i++) {
        int idx = tid + i * 256;
        int r = idx >> 4, c = (idx & 15) << 2;
        *(float4*)(&sQ [r][c]) = *(const float4*)(qb + r * 64 + c);
        *(float4*)(&sKV[r][c]) = *(const float4*)(kb + r * 64 + c);
    }
    __syncthreads();

    int s = tid >> 2, q = tid & 3;
    float4 qv[16];
    #pragma unroll
    for (int k4 = 0; k4 < 16; k4++) qv[k4] = *(const float4*)(&sQ[s][k4 * 4]);

    float sc[16];
    #pragma unroll
    for (int j = 0; j < 16; j++) {
        int t = q + 4 * j;
        float d = 0.f;
        #pragma unroll
        for (int k4 = 0; k4 < 16; k4++) {
            float4 kv = *(const float4*)(&sKV[t][k4 * 4]);
            d += qv[k4].x * kv.x + qv[k4].y * kv.y + qv[k4].z * kv.z + qv[k4].w * kv.w;
        }
        sc[j] = (t <= s) ? d * 0.125f : -1e30f;
    }
    float mx = sc[0];
    #pragma unroll
    for (int j = 1; j < 16; j++) mx = fmaxf(mx, sc[j]);
    mx = fmaxf(mx, __shfl_xor_sync(0xFFFFFFFFu, mx, 1));
    mx = fmaxf(mx, __shfl_xor_sync(0xFFFFFFFFu, mx, 2));
    float sum = 0.f;
    #pragma unroll
    for (int j = 0; j < 16; j++) { sc[j] = __expf(sc[j] - mx); sum += sc[j]; }
    sum += __shfl_xor_sync(0xFFFFFFFFu, sum, 1);
    sum += __shfl_xor_sync(0xFFFFFFFFu, sum, 2);
    float inv = 1.f / sum;
    #pragma unroll
    for (int j = 0; j < 16; j++) sc[j] *= inv;

    __syncthreads();
    #pragma unroll
    for (int i = 0; i < 4; i++) {
        int idx = tid + i * 256;
        int r = idx >> 4, c = (idx & 15) << 2;
        *(float4*)(&sKV[r][c]) = *(const float4*)(vb + r * 64 + c);
    }
    __syncthreads();

    float po[64];
    #pragma unroll
    for (int e = 0; e < 64; e++) po[e] = 0.f;
    #pragma unroll
    for (int j = 0; j < 16; j++) {
        int t = q + 4 * j;
        float w = sc[j];
        #pragma unroll
        for (int e4 = 0; e4 < 16; e4++) {
            float4 v = *(const float4*)(&sKV[t][e4 * 4]);
            po[e4 * 4 + 0] += w * v.x;
            po[e4 * 4 + 1] += w * v.y;
            po[e4 * 4 + 2] += w * v.z;
            po[e4 * 4 + 3] += w * v.w;
        }
    }
    #pragma unroll
    for (int e = 0; e < 64; e++) {
        po[e] += __shfl_xor_sync(0xFFFFFFFFu, po[e], 1);
        po[e] += __shfl_xor_sync(0xFFFFFFFFu, po[e], 2);
    }
    // fused cat-split: this thread owns row (b,s), cols h*64 + [16q, 16q+16)
    int b = bh >> 4, h = bh & 15;
    int row = b * SEQ + s;
    size_t base = (size_t)row * K_EFF + h * HDIM + q * 16;
    #pragma unroll
    for (int i = 0; i < 8; i++) {
        int e0 = q * 16 + i * 2;
        __half2 lo;
        __half2 hi = split_hi2(po[e0], po[e0 + 1], lo);
        *(__half2*)(g_A2 + base + i * 2)        = hi;
        *(__half2*)(g_A2 + base + 1024 + i * 2) = lo;
    }
}

// ---------------- QKV on HMMA: [emb-split] @ fp16([Wq|Wk|Wv]) ----------------
__global__ void __launch_bounds__(256, 2) qkv_mma(const float* __restrict__ bq,
                                                  const float* __restrict__ bk,
                                                  const float* __restrict__ bv)
{
    extern __shared__ char sm[];
    const int tid = threadIdx.x, lane = tid & 31, wid = tid >> 5;
    const int wm = (wid & 1) * 64, wn = (wid >> 1) * 32;
    const int m0 = blockIdx.x * 128;
    const int n0 = blockIdx.y * 128;     // global n in [0, 3072)

    float acc[4][4][4];
    hmma_loop(g_A2 + (size_t)m0 * K_EFF, K_EFF,
              g_Bqkv + (size_t)n0 * KB_DIM, NK_QKV,
              sm, acc, tid, lane, wm, wn);

    const int which = n0 >> 10;          // uniform per CTA
    float* outp = (which == 0) ? g_q : (which == 1) ? g_k : g_v;
    const float* bias = (which == 0) ? bq : (which == 1) ? bk : bv;

    const int er = lane >> 2;
    const int ec = (lane & 3) * 2;
    #pragma unroll
    for (int mi = 0; mi < 4; mi++) {
        #pragma unroll
        for (int nj = 0; nj < 4; nj++) {
            int col = n0 + wn + nj * 8 + ec;      // global
            int n   = col & 1023;                  // within weight
            int h = n >> 6, e = n & 63;
            float b0v = bias[n], b1v = bias[n + 1];
            int row0 = m0 + wm + mi * 16 + er;
            #pragma unroll
            for (int half = 0; half < 2; half++) {
                int row = row0 + half * 8;
                int b = row >> 6, s = row & 63;
                float* dst = outp + (size_t)(((b * NHEAD + h) * SEQ + s) * HDIM + e);
                *(float2*)dst = make_float2(acc[mi][nj][half * 2] + b0v,
                                            acc[mi][nj][half * 2 + 1] + b1v);
            }
        }
    }
}

// ---------------- Wo on HMMA: y = cat-split @ fp16(Wo) + bo + emb; emit fp16(y) ----------------
__global__ void __launch_bounds__(256, 2) wo_mma(const float* __restrict__ bo)
{
    extern __shared__ char sm[];
    const int tid = threadIdx.x, lane = tid & 31, wid = tid >> 5;
    const int wm = (wid & 1) * 64, wn = (wid >> 1) * 32;
    const int m0 = blockIdx.x * 128;
    const int n0 = blockIdx.y * 128;

    float acc[4][4][4];
    hmma_loop(g_A2 + (size_t)m0 * K_EFF, K_EFF,
              g_Bwo + (size_t)n0 * KB_DIM, NK_QKV,
              sm, acc, tid, lane, wm, wn);

    const int er = lane >> 2;
    const int ec = (lane & 3) * 2;
    #pragma unroll
    for (int mi = 0; mi < 4; mi++) {
        #pragma unroll
        for (int nj = 0; nj < 4; nj++) {
            int col = n0 + wn + nj * 8 + ec;
            float b0v = bo[col], b1v = bo[col + 1];
            int row0 = m0 + wm + mi * 16 + er;
            #pragma unroll
            for (int half = 0; half < 2; half++) {
                int row = row0 + half * 8;
                float2 em = *(const float2*)(g_emb + (size_t)row * EMBED + col);
                float y0 = acc[mi][nj][half * 2]     + b0v + em.x;
                float y1 = acc[mi][nj][half * 2 + 1] + b1v + em.y;
                *(__half2*)(g_A3 + (size_t)row * KB_DIM + col) =
                    __half2(__float2half_rn(y0), __float2half_rn(y1));
            }
        }
    }
}

// ---------------- logits on HMMA 128x128: out = fp16(y) @ fp16(Wu) + bu ----------------
// out rows have odd stride (VOCAB) -> scalar stores only.
__global__ void __launch_bounds__(256, 2) wu_mma(const float* __restrict__ bu,
                                                 float* __restrict__ out)
{
    extern __shared__ char sm[];
    const int tid = threadIdx.x, lane = tid & 31, wid = tid >> 5;
    const int wm = (wid & 1) * 64, wn = (wid >> 1) * 32;
    const int m0 = blockIdx.x * 128;
    const int n0 = blockIdx.y * 128;

    float acc[4][4][4];
    hmma_loop(g_A3 + (size_t)m0 * KB_DIM, KB_DIM,
              g_B2 + (size_t)n0 * KB_DIM, NK_WU,
              sm, acc, tid, lane, wm, wn);

    const int er = lane >> 2;
    const int ec = (lane & 3) * 2;
    #pragma unroll
    for (int mi = 0; mi < 4; mi++) {
        #pragma unroll
        for (int nj = 0; nj < 4; nj++) {
            int col = n0 + wn + nj * 8 + ec;
            float b0v = (col < VOCAB)     ? __ldg(bu + col)     : 0.f;
            float b1v = (col + 1 < VOCAB) ? __ldg(bu + col + 1) : 0.f;
            int row = m0 + wm + mi * 16 + er;
            float* p0 = out + (size_t)row * VOCAB + col;
            float* p1 = out + (size_t)(row + 8) * VOCAB + col;
            if (col < VOCAB) {
                p0[0] = acc[mi][nj][0] + b0v;
                p1[0] = acc[mi][nj][2] + b0v;
            }
            if (col + 1 < VOCAB) {
                p0[1] = acc[mi][nj][1] + b1v;
                p1[1] = acc[mi][nj][3] + b1v;
            }
        }
    }
}

// ---------------- launch ----------------
#define MMA_SMEM (3 * STG_SZ)   /* 98304 */

extern "C" void kernel_launch(void* const* d_in, const int* in_sizes, int n_in,
                              void* d_out, int out_size)
{
    const int*   x  = (const int*)  d_in[0];
    const float* E  = (const float*)d_in[1];
    const float* pe = (const float*)d_in[2];
    const float* Wq = (const float*)d_in[3];
    const float* bq = (const float*)d_in[4];
    const float* Wk = (const float*)d_in[5];
    const float* bk = (const float*)d_in[6];
    const float* Wv = (const float*)d_in[7];
    const float* bv = (const float*)d_in[8];
    const float* Wo = (const float*)d_in[9];
    const float* bo = (const float*)d_in[10];
    const float* Wu = (const float*)d_in[11];
    const float* bu = (const float*)d_in[12];
    float* out = (float*)d_out;

    cudaFuncSetAttribute(qkv_mma, cudaFuncAttributeMaxDynamicSharedMemorySize, MMA_SMEM);
    cudaFuncSetAttribute(wo_mma,  cudaFuncAttributeMaxDynamicSharedMemorySize, MMA_SMEM);
    cudaFuncSetAttribute(wu_mma,  cudaFuncAttributeMaxDynamicSharedMemorySize, MMA_SMEM);

    embed_kernel<<<4096, 256>>>(x, E, pe);                              // emb + emb-split
    conv_w_qkv<<<dim3(32, 32, 3), dim3(32, 8)>>>(Wq, Wk, Wv);           // weight fp16
    conv_w_o  <<<dim3(32, 32),    dim3(32, 8)>>>(Wo);
    conv_wu_kernel<<<dim3(N_PAD / 32, EMBED / 32), dim3(32, 8)>>>(Wu);

    qkv_mma<<<dim3(32, 24), 256, MMA_SMEM>>>(bq, bk, bv);               // q,k,v

    attn_kernel<<<BATCH * NHEAD, 256>>>();                              // -> cat-split in g_A2

    wo_mma<<<dim3(32, 8), 256, MMA_SMEM>>>(bo);                         // y-hi -> g_A3

    wu_mma<<<dim3(32, N_PAD / 128), 256, MMA_SMEM>>>(bu, out);          // logits
}

// round 14
// speedup vs baseline: 1.2034x; 1.0758x over previous
#include <cuda_runtime.h>
#include <cuda_fp16.h>
#include <cstdint>

#define BATCH 64
#define SEQ   64
#define EMBED 1024
#define NHEAD 16
#define HDIM  64
#define VOCAB 50257
#define M_TOT (BATCH*SEQ)   /* 4096 */

#define N_PAD  50304        /* 393*128 */
#define KB_DIM 1024         /* K for all GEMMs (pure fp16 pipeline) */
#define NK     16           /* KB_DIM / 64 */

// ---------------- scratch (no allocation allowed) ----------------
__device__ float g_emb[M_TOT*EMBED];
__device__ float g_q  [M_TOT*EMBED];
__device__ float g_k  [M_TOT*EMBED];
__device__ float g_v  [M_TOT*EMBED];
// fp16 operands (K-major, stride KB_DIM)
__device__ __align__(16) __half g_A2  [(size_t)M_TOT * KB_DIM];   // fp16(emb), then fp16(cat)
__device__ __align__(16) __half g_A3  [(size_t)M_TOT * KB_DIM];   // fp16(y)
__device__ __align__(16) __half g_Bqkv[(size_t)3072  * KB_DIM];   // [Wq|Wk|Wv]
__device__ __align__(16) __half g_Bwo [(size_t)EMBED * KB_DIM];   // Wo
__device__ __align__(16) __half g_B2  [(size_t)N_PAD * KB_DIM];   // Wu

// ---------------- helpers ----------------
__device__ __forceinline__ uint32_t smem_u32(const void* p) {
    uint32_t a;
    asm("{ .reg .u64 t; cvta.to.shared.u64 t, %1; cvt.u32.u64 %0, t; }" : "=r"(a) : "l"(p));
    return a;
}
__device__ __forceinline__ void cp16(uint32_t dst, const void* src) {
    asm volatile("cp.async.cg.shared.global [%0], [%1], 16;" :: "r"(dst), "l"(src) : "memory");
}
#define CP_COMMIT() asm volatile("cp.async.commit_group;" ::: "memory")
#define CP_WAIT(N)  asm volatile("cp.async.wait_group %0;" :: "n"(N) : "memory")

__device__ __forceinline__ void ldm_x4(uint32_t (&r)[4], uint32_t addr) {
    asm volatile("ldmatrix.sync.aligned.m8n8.x4.shared.b16 {%0,%1,%2,%3}, [%4];"
        : "=r"(r[0]), "=r"(r[1]), "=r"(r[2]), "=r"(r[3]) : "r"(addr));
}
__device__ __forceinline__ void mma_f16(float (&d)[4], const uint32_t (&a)[4],
                                        uint32_t b0, uint32_t b1) {
    asm volatile("mma.sync.aligned.m16n8k16.row.col.f32.f16.f16.f32 "
        "{%0,%1,%2,%3}, {%4,%5,%6,%7}, {%8,%9}, {%0,%1,%2,%3};"
        : "+f"(d[0]), "+f"(d[1]), "+f"(d[2]), "+f"(d[3])
        : "r"(a[0]), "r"(a[1]), "r"(a[2]), "r"(a[3]), "r"(b0), "r"(b1));
}

// ================= 128x128 HMMA mainloop (all GEMMs) =================
// k-chunk 64 per stage, 3-stage cp.async ring, 2 CTAs/SM.
// Stage layout (32KB): A [2 sub][128 rows][32 fp16 (64B, XOR swizzled)], B same at +16KB.
#define STG_SZ 32768

__device__ __forceinline__ void fill_stage(uint32_t sbase, const __half* Ab,
                                           const __half* Bb, int kt, int tid)
{
    const int ka = kt * 64;
    #pragma unroll
    for (int i = 0; i < 4; i++) {
        int c = tid + i * 256;                 // 0..1023
        int row = c >> 3, ck = c & 7;
        uint32_t off = (ck >> 2) * 8192 + row * 64 + (((ck & 3) ^ ((row >> 1) & 3)) << 4);
        cp16(sbase + off, Ab + (size_t)row * KB_DIM + ka + ck * 8);
    }
    #pragma unroll
    for (int i = 0; i < 4; i++) {
        int c = tid + i * 256;
        int row = c >> 3, ck = c & 7;
        uint32_t off = 16384 + (ck >> 2) * 8192 + row * 64 + (((ck & 3) ^ ((row >> 1) & 3)) << 4);
        cp16(sbase + off, Bb + (size_t)row * KB_DIM + ka + ck * 8);
    }
}

__device__ __forceinline__ void compute_stage(uint32_t sbase, float (&acc)[4][4][4],
                                              int lane, int wm, int wn)
{
    const int a_r8 = (lane & 7) + ((lane >> 3) & 1) * 8;
    const int a_kh = (lane >> 4) * 8;
    const int b_r8 = (lane & 7) + (lane >> 4) * 8;
    const int b_kh = ((lane >> 3) & 1) * 8;
    #pragma unroll
    for (int sub = 0; sub < 2; sub++) {
        const uint32_t A0 = sbase + sub * 8192;
        const uint32_t B0 = sbase + 16384 + sub * 8192;
        #pragma unroll
        for (int ks = 0; ks < 32; ks += 16) {
            uint32_t af[4][4], bf[4][2];
            #pragma unroll
            for (int mi = 0; mi < 4; mi++) {
                int row = wm + mi * 16 + a_r8;
                int kk  = ks + a_kh;
                ldm_x4(af[mi], A0 + row * 64 + (((kk >> 3) ^ ((row >> 1) & 3)) << 4));
            }
            #pragma unroll
            for (int nj = 0; nj < 2; nj++) {
                int row = wn + nj * 16 + b_r8;
                int kk  = ks + b_kh;
                uint32_t t[4];
                ldm_x4(t, B0 + row * 64 + (((kk >> 3) ^ ((row >> 1) & 3)) << 4));
                bf[nj * 2][0]     = t[0]; bf[nj * 2][1]     = t[1];
                bf[nj * 2 + 1][0] = t[2]; bf[nj * 2 + 1][1] = t[3];
            }
            #pragma unroll
            for (int mi = 0; mi < 4; mi++)
                #pragma unroll
                for (int nj = 0; nj < 4; nj++)
                    mma_f16(acc[mi][nj], af[mi], bf[nj][0], bf[nj][1]);
        }
    }
}

__device__ __forceinline__ void hmma_loop(const __half* Ab, const __half* Bb,
                                          char* sm, float (&acc)[4][4][4],
                                          int tid, int lane, int wm, int wn)
{
    #pragma unroll
    for (int i = 0; i < 4; i++)
        #pragma unroll
        for (int j = 0; j < 4; j++)
            #pragma unroll
            for (int r = 0; r < 4; r++) acc[i][j][r] = 0.f;

    const uint32_t sb = smem_u32(sm);
    fill_stage(sb,          Ab, Bb, 0, tid); CP_COMMIT();
    fill_stage(sb + STG_SZ, Ab, Bb, 1, tid); CP_COMMIT();

    for (int kt = 0; kt < NK; kt++) {
        CP_WAIT(1);                 // in-order completion: group kt is done
        __syncthreads();            // data visible; also guards ring reuse (WAR)
        if (kt + 2 < NK)
            fill_stage(sb + ((kt + 2) % 3) * STG_SZ, Ab, Bb, kt + 2, tid);
        CP_COMMIT();                // keep one group per iter (empty ok)
        compute_stage(sb + (kt % 3) * STG_SZ, acc, lane, wm, wn);
    }
}

// ---------------- embed (+ fused fp16 convert into g_A2) ----------------
__global__ void __launch_bounds__(256) embed_kernel(const int* __restrict__ x,
                                                    const float* __restrict__ E,
                                                    const float* __restrict__ pe)
{
    int idx = blockIdx.x * 256 + threadIdx.x;
    int row = idx >> 8;
    int c   = (idx & 255) << 2;
    int tok = x[row];
    float4 e = *(const float4*)(E  + (size_t)tok * EMBED + c);
    float4 p = *(const float4*)(pe + (size_t)(row & 63) * EMBED + c);
    e.x += p.x; e.y += p.y; e.z += p.z; e.w += p.w;
    *(float4*)(g_emb + (size_t)row * EMBED + c) = e;

    size_t base = (size_t)row * KB_DIM + c;
    *(__half2*)(g_A2 + base)     = __half2(__float2half_rn(e.x), __float2half_rn(e.y));
    *(__half2*)(g_A2 + base + 2) = __half2(__float2half_rn(e.z), __float2half_rn(e.w));
}

// ---------------- weight prepass (all four weights, one launch) ----------------
// z=0..2: Wq/Wk/Wv ([H][D][hd] layout), z=3: Wo ([D][D] row-major)
__global__ void __launch_bounds__(256) conv_w_all(const float* __restrict__ Wq,
                                                  const float* __restrict__ Wk,
                                                  const float* __restrict__ Wv,
                                                  const float* __restrict__ Wo)
{
    __shared__ float t[32][33];
    int z  = blockIdx.z;
    int n0 = blockIdx.x * 32;
    int k0 = blockIdx.y * 32;
    int tx = threadIdx.x, ty = threadIdx.y;   // 32 x 8
    if (z < 3) {
        const float* W = (z == 0) ? Wq : (z == 1) ? Wk : Wv;
        int h = n0 >> 6, e0 = n0 & 63;
        #pragma unroll
        for (int i = 0; i < 4; i++) {
            int kk = ty + i * 8;
            t[kk][tx] = W[(size_t)h * (EMBED * HDIM) + (size_t)(k0 + kk) * HDIM + e0 + tx];
        }
        __syncthreads();
        #pragma unroll
        for (int i = 0; i < 4; i++) {
            int nn = ty + i * 8;
            g_Bqkv[(size_t)(z * 1024 + n0 + nn) * KB_DIM + k0 + tx] =
                __float2half_rn(t[tx][nn]);
        }
    } else {
        #pragma unroll
        for (int i = 0; i < 4; i++) {
            int kk = ty + i * 8;
            t[kk][tx] = Wo[(size_t)(k0 + kk) * EMBED + n0 + tx];
        }
        __syncthreads();
        #pragma unroll
        for (int i = 0; i < 4; i++) {
            int nn = ty + i * 8;
            g_Bwo[(size_t)(n0 + nn) * KB_DIM + k0 + tx] = __float2half_rn(t[tx][nn]);
        }
    }
}

// Wu: [1024 k][VOCAB n] (odd stride -> scalar loads) -> g_B2[n][k]
__global__ void __launch_bounds__(256) conv_wu_kernel(const float* __restrict__ Wu)
{
    __shared__ float t[32][33];
    int n0 = blockIdx.x * 32;
    int k0 = blockIdx.y * 32;
    int tx = threadIdx.x, ty = threadIdx.y;
    #pragma unroll
    for (int i = 0; i < 4; i++) {
        int k = k0 + ty + i * 8;
        int n = n0 + tx;
        t[ty + i * 8][tx] = (n < VOCAB) ? Wu[(size_t)k * VOCAB + n] : 0.f;
    }
    __syncthreads();
    #pragma unroll
    for (int i = 0; i < 4; i++) {
        int n = n0 + ty + i * 8;
        int k = k0 + tx;
        g_B2[(size_t)n * KB_DIM + k] = __float2half_rn(t[tx][ty + i * 8]);
    }
}

// ---------------- attention (fp32) + fused fp16 cat into g_A2 ----------------
__global__ void __launch_bounds__(256) attn_kernel()
{
    __shared__ float sQ [64][68];
    __shared__ float sKV[64][68];
    int bh  = blockIdx.x;
    int tid = threadIdx.x;
    const float* qb = g_q + (size_t)bh * (SEQ * HDIM);
    const float* kb = g_k + (size_t)bh * (SEQ * HDIM);
    const float* vb = g_v + (size_t)bh * (SEQ * HDIM);
    #pragma unroll
    for (int i = 0; i < 4; i++) {
        int idx = tid + i * 256;
        int r = idx >> 4, c = (idx & 15) << 2;
        *(float4*)(&sQ [r][c]) = *(const float4*)(qb + r * 64 + c);
        *(float4*)(&sKV[r][c]) = *(const float4*)(kb + r * 64 + c);
    }
    __syncthreads();

    int s = tid >> 2, q = tid & 3;
    float4 qv[16];
    #pragma unroll
    for (int k4 = 0; k4 < 16; k4++) qv[k4] = *(const float4*)(&sQ[s][k4 * 4]);

    float sc[16];
    #pragma unroll
    for (int j = 0; j < 16; j++) {
        int t = q + 4 * j;
        float d = 0.f;
        #pragma unroll
        for (int k4 = 0; k4 < 16; k4++) {
            float4 kv = *(const float4*)(&sKV[t][k4 * 4]);
            d += qv[k4].x * kv.x + qv[k4].y * kv.y + qv[k4].z * kv.z + qv[k4].w * kv.w;
        }
        sc[j] = (t <= s) ? d * 0.125f : -1e30f;
    }
    float mx = sc[0];
    #pragma unroll
    for (int j = 1; j < 16; j++) mx = fmaxf(mx, sc[j]);
    mx = fmaxf(mx, __shfl_xor_sync(0xFFFFFFFFu, mx, 1));
    mx = fmaxf(mx, __shfl_xor_sync(0xFFFFFFFFu, mx, 2));
    float sum = 0.f;
    #pragma unroll
    for (int j = 0; j < 16; j++) { sc[j] = __expf(sc[j] - mx); sum += sc[j]; }
    sum += __shfl_xor_sync(0xFFFFFFFFu, sum, 1);
    sum += __shfl_xor_sync(0xFFFFFFFFu, sum, 2);
    float inv = 1.f / sum;
    #pragma unroll
    for (int j = 0; j < 16; j++) sc[j] *= inv;

    __syncthreads();
    #pragma unroll
    for (int i = 0; i < 4; i++) {
        int idx = tid + i * 256;
        int r = idx >> 4, c = (idx & 15) << 2;
        *(float4*)(&sKV[r][c]) = *(const float4*)(vb + r * 64 + c);
    }
    __syncthreads();

    float po[64];
    #pragma unroll
    for (int e = 0; e < 64; e++) po[e] = 0.f;
    #pragma unroll
    for (int j = 0; j < 16; j++) {
        int t = q + 4 * j;
        float w = sc[j];
        #pragma unroll
        for (int e4 = 0; e4 < 16; e4++) {
            float4 v = *(const float4*)(&sKV[t][e4 * 4]);
            po[e4 * 4 + 0] += w * v.x;
            po[e4 * 4 + 1] += w * v.y;
            po[e4 * 4 + 2] += w * v.z;
            po[e4 * 4 + 3] += w * v.w;
        }
    }
    #pragma unroll
    for (int e = 0; e < 64; e++) {
        po[e] += __shfl_xor_sync(0xFFFFFFFFu, po[e], 1);
        po[e] += __shfl_xor_sync(0xFFFFFFFFu, po[e], 2);
    }
    // fused fp16 cat: this thread owns row (b,s), cols h*64 + [16q, 16q+16)
    int b = bh >> 4, h = bh & 15;
    int row = b * SEQ + s;
    size_t base = (size_t)row * KB_DIM + h * HDIM + q * 16;
    #pragma unroll
    for (int i = 0; i < 8; i++) {
        int e0 = q * 16 + i * 2;
        *(__half2*)(g_A2 + base + i * 2) =
            __half2(__float2half_rn(po[e0]), __float2half_rn(po[e0 + 1]));
    }
}

// ---------------- QKV on HMMA: fp16(emb) @ fp16([Wq|Wk|Wv]) ----------------
__global__ void __launch_bounds__(256, 2) qkv_mma(const float* __restrict__ bq,
                                                  const float* __restrict__ bk,
                                                  const float* __restrict__ bv)
{
    extern __shared__ char sm[];
    const int tid = threadIdx.x, lane = tid & 31, wid = tid >> 5;
    const int wm = (wid & 1) * 64, wn = (wid >> 1) * 32;
    const int m0 = blockIdx.x * 128;
    const int n0 = blockIdx.y * 128;     // global n in [0, 3072)

    float acc[4][4][4];
    hmma_loop(g_A2 + (size_t)m0 * KB_DIM, g_Bqkv + (size_t)n0 * KB_DIM,
              sm, acc, tid, lane, wm, wn);

    const int which = n0 >> 10;          // uniform per CTA
    float* outp = (which == 0) ? g_q : (which == 1) ? g_k : g_v;
    const float* bias = (which == 0) ? bq : (which == 1) ? bk : bv;

    const int er = lane >> 2;
    const int ec = (lane & 3) * 2;
    #pragma unroll
    for (int mi = 0; mi < 4; mi++) {
        #pragma unroll
        for (int nj = 0; nj < 4; nj++) {
            int col = n0 + wn + nj * 8 + ec;      // global
            int n   = col & 1023;                  // within weight
            int h = n >> 6, e = n & 63;
            float b0v = bias[n], b1v = bias[n + 1];
            int row0 = m0 + wm + mi * 16 + er;
            #pragma unroll
            for (int half = 0; half < 2; half++) {
                int row = row0 + half * 8;
                int b = row >> 6, s = row & 63;
                float* dst = outp + (size_t)(((b * NHEAD + h) * SEQ + s) * HDIM + e);
                *(float2*)dst = make_float2(acc[mi][nj][half * 2] + b0v,
                                            acc[mi][nj][half * 2 + 1] + b1v);
            }
        }
    }
}

// ---------------- Wo on HMMA: y = fp16(cat) @ fp16(Wo) + bo + emb; emit fp16(y) ----------------
__global__ void __launch_bounds__(256, 2) wo_mma(const float* __restrict__ bo)
{
    extern __shared__ char sm[];
    const int tid = threadIdx.x, lane = tid & 31, wid = tid >> 5;
    const int wm = (wid & 1) * 64, wn = (wid >> 1) * 32;
    const int m0 = blockIdx.x * 128;
    const int n0 = blockIdx.y * 128;

    float acc[4][4][4];
    hmma_loop(g_A2 + (size_t)m0 * KB_DIM, g_Bwo + (size_t)n0 * KB_DIM,
              sm, acc, tid, lane, wm, wn);

    const int er = lane >> 2;
    const int ec = (lane & 3) * 2;
    #pragma unroll
    for (int mi = 0; mi < 4; mi++) {
        #pragma unroll
        for (int nj = 0; nj < 4; nj++) {
            int col = n0 + wn + nj * 8 + ec;
            float b0v = bo[col], b1v = bo[col + 1];
            int row0 = m0 + wm + mi * 16 + er;
            #pragma unroll
            for (int half = 0; half < 2; half++) {
                int row = row0 + half * 8;
                float2 em = *(const float2*)(g_emb + (size_t)row * EMBED + col);
                float y0 = acc[mi][nj][half * 2]     + b0v + em.x;
                float y1 = acc[mi][nj][half * 2 + 1] + b1v + em.y;
                *(__half2*)(g_A3 + (size_t)row * KB_DIM + col) =
                    __half2(__float2half_rn(y0), __float2half_rn(y1));
            }
        }
    }
}

// ---------------- logits on HMMA: out = fp16(y) @ fp16(Wu) + bu ----------------
// out rows have odd stride (VOCAB) -> scalar stores only.
__global__ void __launch_bounds__(256, 2) wu_mma(const float* __restrict__ bu,
                                                 float* __restrict__ out)
{
    extern __shared__ char sm[];
    const int tid = threadIdx.x, lane = tid & 31, wid = tid >> 5;
    const int wm = (wid & 1) * 64, wn = (wid >> 1) * 32;
    const int m0 = blockIdx.x * 128;
    const int n0 = blockIdx.y * 128;

    float acc[4][4][4];
    hmma_loop(g_A3 + (size_t)m0 * KB_DIM, g_B2 + (size_t)n0 * KB_DIM,
              sm, acc, tid, lane, wm, wn);

    const int er = lane >> 2;
    const int ec = (lane & 3) * 2;
    #pragma unroll
    for (int mi = 0; mi < 4; mi++) {
        #pragma unroll
        for (int nj = 0; nj < 4; nj++) {
            int col = n0 + wn + nj * 8 + ec;
            float b0v = (col < VOCAB)     ? __ldg(bu + col)     : 0.f;
            float b1v = (col + 1 < VOCAB) ? __ldg(bu + col + 1) : 0.f;
            int row = m0 + wm + mi * 16 + er;
            float* p0 = out + (size_t)row * VOCAB + col;
            float* p1 = out + (size_t)(row + 8) * VOCAB + col;
            if (col < VOCAB) {
                p0[0] = acc[mi][nj][0] + b0v;
                p1[0] = acc[mi][nj][2] + b0v;
            }
            if (col + 1 < VOCAB) {
                p0[1] = acc[mi][nj][1] + b1v;
                p1[1] = acc[mi][nj][3] + b1v;
            }
        }
    }
}

// ---------------- launch ----------------
#define MMA_SMEM (3 * STG_SZ)   /* 98304 */

extern "C" void kernel_launch(void* const* d_in, const int* in_sizes, int n_in,
                              void* d_out, int out_size)
{
    const int*   x  = (const int*)  d_in[0];
    const float* E  = (const float*)d_in[1];
    const float* pe = (const float*)d_in[2];
    const float* Wq = (const float*)d_in[3];
    const float* bq = (const float*)d_in[4];
    const float* Wk = (const float*)d_in[5];
    const float* bk = (const float*)d_in[6];
    const float* Wv = (const float*)d_in[7];
    const float* bv = (const float*)d_in[8];
    const float* Wo = (const float*)d_in[9];
    const float* bo = (const float*)d_in[10];
    const float* Wu = (const float*)d_in[11];
    const float* bu = (const float*)d_in[12];
    float* out = (float*)d_out;

    cudaFuncSetAttribute(qkv_mma, cudaFuncAttributeMaxDynamicSharedMemorySize, MMA_SMEM);
    cudaFuncSetAttribute(wo_mma,  cudaFuncAttributeMaxDynamicSharedMemorySize, MMA_SMEM);
    cudaFuncSetAttribute(wu_mma,  cudaFuncAttributeMaxDynamicSharedMemorySize, MMA_SMEM);

    embed_kernel<<<4096, 256>>>(x, E, pe);                              // emb + fp16(emb)
    conv_w_all<<<dim3(32, 32, 4), dim3(32, 8)>>>(Wq, Wk, Wv, Wo);       // weight fp16
    conv_wu_kernel<<<dim3(N_PAD / 32, EMBED / 32), dim3(32, 8)>>>(Wu);

    qkv_mma<<<dim3(32, 24), 256, MMA_SMEM>>>(bq, bk, bv);               // q,k,v

    attn_kernel<<<BATCH * NHEAD, 256>>>();                              // -> fp16(cat) in g_A2

    wo_mma<<<dim3(32, 8), 256, MMA_SMEM>>>(bo);                         // fp16(y) -> g_A3

    wu_mma<<<dim3(32, N_PAD / 128), 256, MMA_SMEM>>>(bu, out);          // logits
}

// round 15
// speedup vs baseline: 1.2366x; 1.0276x over previous
#include <cuda_runtime.h>
#include <cuda_fp16.h>
#include <cstdint>

#define BATCH 64
#define SEQ   64
#define EMBED 1024
#define NHEAD 16
#define HDIM  64
#define VOCAB 50257
#define M_TOT (BATCH*SEQ)   /* 4096 */

#define N_PAD  50304        /* 393*128 */
#define KB_DIM 1024         /* K for all GEMMs (pure fp16 pipeline) */
#define NK     16           /* KB_DIM / 64 */

// ---------------- scratch (no allocation allowed) ----------------
__device__ float g_emb[M_TOT*EMBED];
__device__ float g_q  [M_TOT*EMBED];
__device__ float g_k  [M_TOT*EMBED];
__device__ float g_v  [M_TOT*EMBED];
// fp16 operands (K-major, stride KB_DIM)
__device__ __align__(16) __half g_A2  [(size_t)M_TOT * KB_DIM];   // fp16(emb), then fp16(cat)
__device__ __align__(16) __half g_A3  [(size_t)M_TOT * KB_DIM];   // fp16(y)
__device__ __align__(16) __half g_Bqkv[(size_t)3072  * KB_DIM];   // [Wq|Wk|Wv]
__device__ __align__(16) __half g_Bwo [(size_t)EMBED * KB_DIM];   // Wo
__device__ __align__(16) __half g_B2  [(size_t)N_PAD * KB_DIM];   // Wu

// ---------------- helpers ----------------
__device__ __forceinline__ uint32_t smem_u32(const void* p) {
    uint32_t a;
    asm("{ .reg .u64 t; cvta.to.shared.u64 t, %1; cvt.u32.u64 %0, t; }" : "=r"(a) : "l"(p));
    return a;
}
__device__ __forceinline__ void cp16(uint32_t dst, const void* src) {
    asm volatile("cp.async.cg.shared.global [%0], [%1], 16;" :: "r"(dst), "l"(src) : "memory");
}
#define CP_COMMIT() asm volatile("cp.async.commit_group;" ::: "memory")
#define CP_WAIT(N)  asm volatile("cp.async.wait_group %0;" :: "n"(N) : "memory")

__device__ __forceinline__ void ldm_x4(uint32_t (&r)[4], uint32_t addr) {
    asm volatile("ldmatrix.sync.aligned.m8n8.x4.shared.b16 {%0,%1,%2,%3}, [%4];"
        : "=r"(r[0]), "=r"(r[1]), "=r"(r[2]), "=r"(r[3]) : "r"(addr));
}
__device__ __forceinline__ void mma_f16(float (&d)[4], const uint32_t (&a)[4],
                                        uint32_t b0, uint32_t b1) {
    asm volatile("mma.sync.aligned.m16n8k16.row.col.f32.f16.f16.f32 "
        "{%0,%1,%2,%3}, {%4,%5,%6,%7}, {%8,%9}, {%0,%1,%2,%3};"
        : "+f"(d[0]), "+f"(d[1]), "+f"(d[2]), "+f"(d[3])
        : "r"(a[0]), "r"(a[1]), "r"(a[2]), "r"(a[3]), "r"(b0), "r"(b1));
}

// ================= 128x128 HMMA mainloop, 8 warps (qkv / wo) =================
// k-chunk 64 per stage, 3-stage cp.async ring, 2 CTAs/SM.
// Stage layout (32KB): A [2 sub][128 rows][32 fp16 (64B, XOR swizzled)], B same at +16KB.
#define STG_SZ 32768

__device__ __forceinline__ void fill_stage(uint32_t sbase, const __half* Ab,
                                           const __half* Bb, int kt, int tid)
{
    const int ka = kt * 64;
    #pragma unroll
    for (int i = 0; i < 4; i++) {
        int c = tid + i * 256;                 // 0..1023
        int row = c >> 3, ck = c & 7;
        uint32_t off = (ck >> 2) * 8192 + row * 64 + (((ck & 3) ^ ((row >> 1) & 3)) << 4);
        cp16(sbase + off, Ab + (size_t)row * KB_DIM + ka + ck * 8);
    }
    #pragma unroll
    for (int i = 0; i < 4; i++) {
        int c = tid + i * 256;
        int row = c >> 3, ck = c & 7;
        uint32_t off = 16384 + (ck >> 2) * 8192 + row * 64 + (((ck & 3) ^ ((row >> 1) & 3)) << 4);
        cp16(sbase + off, Bb + (size_t)row * KB_DIM + ka + ck * 8);
    }
}

__device__ __forceinline__ void compute_stage(uint32_t sbase, float (&acc)[4][4][4],
                                              int lane, int wm, int wn)
{
    const int a_r8 = (lane & 7) + ((lane >> 3) & 1) * 8;
    const int a_kh = (lane >> 4) * 8;
    const int b_r8 = (lane & 7) + (lane >> 4) * 8;
    const int b_kh = ((lane >> 3) & 1) * 8;
    #pragma unroll
    for (int sub = 0; sub < 2; sub++) {
        const uint32_t A0 = sbase + sub * 8192;
        const uint32_t B0 = sbase + 16384 + sub * 8192;
        #pragma unroll
        for (int ks = 0; ks < 32; ks += 16) {
            uint32_t af[4][4], bf[4][2];
            #pragma unroll
            for (int mi = 0; mi < 4; mi++) {
                int row = wm + mi * 16 + a_r8;
                int kk  = ks + a_kh;
                ldm_x4(af[mi], A0 + row * 64 + (((kk >> 3) ^ ((row >> 1) & 3)) << 4));
            }
            #pragma unroll
            for (int nj = 0; nj < 2; nj++) {
                int row = wn + nj * 16 + b_r8;
                int kk  = ks + b_kh;
                uint32_t t[4];
                ldm_x4(t, B0 + row * 64 + (((kk >> 3) ^ ((row >> 1) & 3)) << 4));
                bf[nj * 2][0]     = t[0]; bf[nj * 2][1]     = t[1];
                bf[nj * 2 + 1][0] = t[2]; bf[nj * 2 + 1][1] = t[3];
            }
            #pragma unroll
            for (int mi = 0; mi < 4; mi++)
                #pragma unroll
                for (int nj = 0; nj < 4; nj++)
                    mma_f16(acc[mi][nj], af[mi], bf[nj][0], bf[nj][1]);
        }
    }
}

__device__ __forceinline__ void hmma_loop(const __half* Ab, const __half* Bb,
                                          char* sm, float (&acc)[4][4][4],
                                          int tid, int lane, int wm, int wn)
{
    #pragma unroll
    for (int i = 0; i < 4; i++)
        #pragma unroll
        for (int j = 0; j < 4; j++)
            #pragma unroll
            for (int r = 0; r < 4; r++) acc[i][j][r] = 0.f;

    const uint32_t sb = smem_u32(sm);
    fill_stage(sb,          Ab, Bb, 0, tid); CP_COMMIT();
    fill_stage(sb + STG_SZ, Ab, Bb, 1, tid); CP_COMMIT();

    for (int kt = 0; kt < NK; kt++) {
        CP_WAIT(1);                 // in-order completion: group kt is done
        __syncthreads();            // data visible; also guards ring reuse (WAR)
        if (kt + 2 < NK)
            fill_stage(sb + ((kt + 2) % 3) * STG_SZ, Ab, Bb, kt + 2, tid);
        CP_COMMIT();                // keep one group per iter (empty ok)
        compute_stage(sb + (kt % 3) * STG_SZ, acc, lane, wm, wn);
    }
}

// ================= 128x128 HMMA mainloop, 4 warps / warp tile 64x64 (wu) =================
// Same 32KB stage + 3-stage ring; 128 threads -> 256 regs/thread budget, so the
// fragment sets double-buffer in registers and ldmatrix overlaps mma.
__device__ __forceinline__ void fill_stage_w4(uint32_t sbase, const __half* Ab,
                                              const __half* Bb, int kt, int tid)
{
    const int ka = kt * 64;
    #pragma unroll
    for (int i = 0; i < 8; i++) {
        int c = tid + i * 128;                 // 0..1023
        int row = c >> 3, ck = c & 7;
        uint32_t off = (ck >> 2) * 8192 + row * 64 + (((ck & 3) ^ ((row >> 1) & 3)) << 4);
        cp16(sbase + off, Ab + (size_t)row * KB_DIM + ka + ck * 8);
    }
    #pragma unroll
    for (int i = 0; i < 8; i++) {
        int c = tid + i * 128;
        int row = c >> 3, ck = c & 7;
        uint32_t off = 16384 + (ck >> 2) * 8192 + row * 64 + (((ck & 3) ^ ((row >> 1) & 3)) << 4);
        cp16(sbase + off, Bb + (size_t)row * KB_DIM + ka + ck * 8);
    }
}

__device__ __forceinline__ void compute_stage_w4(uint32_t sbase, float (&acc)[4][8][4],
                                                 int lane, int wm, int wn)
{
    const int a_r8 = (lane & 7) + ((lane >> 3) & 1) * 8;
    const int a_kh = (lane >> 4) * 8;
    const int b_r8 = (lane & 7) + (lane >> 4) * 8;
    const int b_kh = ((lane >> 3) & 1) * 8;
    #pragma unroll
    for (int sub = 0; sub < 2; sub++) {
        const uint32_t A0 = sbase + sub * 8192;
        const uint32_t B0 = sbase + 16384 + sub * 8192;
        #pragma unroll
        for (int ks = 0; ks < 32; ks += 16) {
            uint32_t af[4][4], bf[8][2];
            #pragma unroll
            for (int mi = 0; mi < 4; mi++) {
                int row = wm + mi * 16 + a_r8;
                int kk  = ks + a_kh;
                ldm_x4(af[mi], A0 + row * 64 + (((kk >> 3) ^ ((row >> 1) & 3)) << 4));
            }
            #pragma unroll
            for (int njj = 0; njj < 4; njj++) {
                int row = wn + njj * 16 + b_r8;
                int kk  = ks + b_kh;
                uint32_t t[4];
                ldm_x4(t, B0 + row * 64 + (((kk >> 3) ^ ((row >> 1) & 3)) << 4));
                bf[njj * 2][0]     = t[0]; bf[njj * 2][1]     = t[1];
                bf[njj * 2 + 1][0] = t[2]; bf[njj * 2 + 1][1] = t[3];
            }
            #pragma unroll
            for (int mi = 0; mi < 4; mi++)
                #pragma unroll
                for (int nj = 0; nj < 8; nj++)
                    mma_f16(acc[mi][nj], af[mi], bf[nj][0], bf[nj][1]);
        }
    }
}

// ---------------- embed (+ fused fp16 convert into g_A2) ----------------
__global__ void __launch_bounds__(256) embed_kernel(const int* __restrict__ x,
                                                    const float* __restrict__ E,
                                                    const float* __restrict__ pe)
{
    int idx = blockIdx.x * 256 + threadIdx.x;
    int row = idx >> 8;
    int c   = (idx & 255) << 2;
    int tok = x[row];
    float4 e = *(const float4*)(E  + (size_t)tok * EMBED + c);
    float4 p = *(const float4*)(pe + (size_t)(row & 63) * EMBED + c);
    e.x += p.x; e.y += p.y; e.z += p.z; e.w += p.w;
    *(float4*)(g_emb + (size_t)row * EMBED + c) = e;

    size_t base = (size_t)row * KB_DIM + c;
    *(__half2*)(g_A2 + base)     = __half2(__float2half_rn(e.x), __float2half_rn(e.y));
    *(__half2*)(g_A2 + base + 2) = __half2(__float2half_rn(e.z), __float2half_rn(e.w));
}

// ---------------- weight prepass (all four weights, one launch) ----------------
__global__ void __launch_bounds__(256) conv_w_all(const float* __restrict__ Wq,
                                                  const float* __restrict__ Wk,
                                                  const float* __restrict__ Wv,
                                                  const float* __restrict__ Wo)
{
    __shared__ float t[32][33];
    int z  = blockIdx.z;
    int n0 = blockIdx.x * 32;
    int k0 = blockIdx.y * 32;
    int tx = threadIdx.x, ty = threadIdx.y;   // 32 x 8
    if (z < 3) {
        const float* W = (z == 0) ? Wq : (z == 1) ? Wk : Wv;
        int h = n0 >> 6, e0 = n0 & 63;
        #pragma unroll
        for (int i = 0; i < 4; i++) {
            int kk = ty + i * 8;
            t[kk][tx] = W[(size_t)h * (EMBED * HDIM) + (size_t)(k0 + kk) * HDIM + e0 + tx];
        }
        __syncthreads();
        #pragma unroll
        for (int i = 0; i < 4; i++) {
            int nn = ty + i * 8;
            g_Bqkv[(size_t)(z * 1024 + n0 + nn) * KB_DIM + k0 + tx] =
                __float2half_rn(t[tx][nn]);
        }
    } else {
        #pragma unroll
        for (int i = 0; i < 4; i++) {
            int kk = ty + i * 8;
            t[kk][tx] = Wo[(size_t)(k0 + kk) * EMBED + n0 + tx];
        }
        __syncthreads();
        #pragma unroll
        for (int i = 0; i < 4; i++) {
            int nn = ty + i * 8;
            g_Bwo[(size_t)(n0 + nn) * KB_DIM + k0 + tx] = __float2half_rn(t[tx][nn]);
        }
    }
}

// Wu: [1024 k][VOCAB n] (odd stride -> scalar loads) -> g_B2[n][k]
__global__ void __launch_bounds__(256) conv_wu_kernel(const float* __restrict__ Wu)
{
    __shared__ float t[32][33];
    int n0 = blockIdx.x * 32;
    int k0 = blockIdx.y * 32;
    int tx = threadIdx.x, ty = threadIdx.y;
    #pragma unroll
    for (int i = 0; i < 4; i++) {
        int k = k0 + ty + i * 8;
        int n = n0 + tx;
        t[ty + i * 8][tx] = (n < VOCAB) ? Wu[(size_t)k * VOCAB + n] : 0.f;
    }
    __syncthreads();
    #pragma unroll
    for (int i = 0; i < 4; i++) {
        int n = n0 + ty + i * 8;
        int k = k0 + tx;
        g_B2[(size_t)n * KB_DIM + k] = __float2half_rn(t[tx][ty + i * 8]);
    }
}

// ---------------- attention (fp32) + fused fp16 cat into g_A2 ----------------
__global__ void __launch_bounds__(256) attn_kernel()
{
    __shared__ float sQ [64][68];
    __shared__ float sKV[64][68];
    int bh  = blockIdx.x;
    int tid = threadIdx.x;
    const float* qb = g_q + (size_t)bh * (SEQ * HDIM);
    const float* kb = g_k + (size_t)bh * (SEQ * HDIM);
    const float* vb = g_v + (size_t)bh * (SEQ * HDIM);
    #pragma unroll
    for (int i = 0; i < 4; i++) {
        int idx = tid + i * 256;
        int r = idx >> 4, c = (idx & 15) << 2;
        *(float4*)(&sQ [r][c]) = *(const float4*)(qb + r * 64 + c);
        *(float4*)(&sKV[r][c]) = *(const float4*)(kb + r * 64 + c);
    }
    __syncthreads();

    int s = tid >> 2, q = tid & 3;
    float4 qv[16];
    #pragma unroll
    for (int k4 = 0; k4 < 16; k4++) qv[k4] = *(const float4*)(&sQ[s][k4 * 4]);

    float sc[16];
    #pragma unroll
    for (int j = 0; j < 16; j++) {
        int t = q + 4 * j;
        float d = 0.f;
        #pragma unroll
        for (int k4 = 0; k4 < 16; k4++) {
            float4 kv = *(const float4*)(&sKV[t][k4 * 4]);
            d += qv[k4].x * kv.x + qv[k4].y * kv.y + qv[k4].z * kv.z + qv[k4].w * kv.w;
        }
        sc[j] = (t <= s) ? d * 0.125f : -1e30f;
    }
    float mx = sc[0];
    #pragma unroll
    for (int j = 1; j < 16; j++) mx = fmaxf(mx, sc[j]);
    mx = fmaxf(mx, __shfl_xor_sync(0xFFFFFFFFu, mx, 1));
    mx = fmaxf(mx, __shfl_xor_sync(0xFFFFFFFFu, mx, 2));
    float sum = 0.f;
    #pragma unroll
    for (int j = 0; j < 16; j++) { sc[j] = __expf(sc[j] - mx); sum += sc[j]; }
    sum += __shfl_xor_sync(0xFFFFFFFFu, sum, 1);
    sum += __shfl_xor_sync(0xFFFFFFFFu, sum, 2);
    float inv = 1.f / sum;
    #pragma unroll
    for (int j = 0; j < 16; j++) sc[j] *= inv;

    __syncthreads();
    #pragma unroll
    for (int i = 0; i < 4; i++) {
        int idx = tid + i * 256;
        int r = idx >> 4, c = (idx & 15) << 2;
        *(float4*)(&sKV[r][c]) = *(const float4*)(vb + r * 64 + c);
    }
    __syncthreads();

    float po[64];
    #pragma unroll
    for (int e = 0; e < 64; e++) po[e] = 0.f;
    #pragma unroll
    for (int j = 0; j < 16; j++) {
        int t = q + 4 * j;
        float w = sc[j];
        #pragma unroll
        for (int e4 = 0; e4 < 16; e4++) {
            float4 v = *(const float4*)(&sKV[t][e4 * 4]);
            po[e4 * 4 + 0] += w * v.x;
            po[e4 * 4 + 1] += w * v.y;
            po[e4 * 4 + 2] += w * v.z;
            po[e4 * 4 + 3] += w * v.w;
        }
    }
    #pragma unroll
    for (int e = 0; e < 64; e++) {
        po[e] += __shfl_xor_sync(0xFFFFFFFFu, po[e], 1);
        po[e] += __shfl_xor_sync(0xFFFFFFFFu, po[e], 2);
    }
    // fused fp16 cat: this thread owns row (b,s), cols h*64 + [16q, 16q+16)
    int b = bh >> 4, h = bh & 15;
    int row = b * SEQ + s;
    size_t base = (size_t)row * KB_DIM + h * HDIM + q * 16;
    #pragma unroll
    for (int i = 0; i < 8; i++) {
        int e0 = q * 16 + i * 2;
        *(__half2*)(g_A2 + base + i * 2) =
            __half2(__float2half_rn(po[e0]), __float2half_rn(po[e0 + 1]));
    }
}

// ---------------- QKV on HMMA: fp16(emb) @ fp16([Wq|Wk|Wv]) ----------------
__global__ void __launch_bounds__(256, 2) qkv_mma(const float* __restrict__ bq,
                                                  const float* __restrict__ bk,
                                                  const float* __restrict__ bv)
{
    extern __shared__ char sm[];
    const int tid = threadIdx.x, lane = tid & 31, wid = tid >> 5;
    const int wm = (wid & 1) * 64, wn = (wid >> 1) * 32;
    const int m0 = blockIdx.x * 128;
    const int n0 = blockIdx.y * 128;     // global n in [0, 3072)

    float acc[4][4][4];
    hmma_loop(g_A2 + (size_t)m0 * KB_DIM, g_Bqkv + (size_t)n0 * KB_DIM,
              sm, acc, tid, lane, wm, wn);

    const int which = n0 >> 10;          // uniform per CTA
    float* outp = (which == 0) ? g_q : (which == 1) ? g_k : g_v;
    const float* bias = (which == 0) ? bq : (which == 1) ? bk : bv;

    const int er = lane >> 2;
    const int ec = (lane & 3) * 2;
    #pragma unroll
    for (int mi = 0; mi < 4; mi++) {
        #pragma unroll
        for (int nj = 0; nj < 4; nj++) {
            int col = n0 + wn + nj * 8 + ec;      // global
            int n   = col & 1023;                  // within weight
            int h = n >> 6, e = n & 63;
            float b0v = bias[n], b1v = bias[n + 1];
            int row0 = m0 + wm + mi * 16 + er;
            #pragma unroll
            for (int half = 0; half < 2; half++) {
                int row = row0 + half * 8;
                int b = row >> 6, s = row & 63;
                float* dst = outp + (size_t)(((b * NHEAD + h) * SEQ + s) * HDIM + e);
                *(float2*)dst = make_float2(acc[mi][nj][half * 2] + b0v,
                                            acc[mi][nj][half * 2 + 1] + b1v);
            }
        }
    }
}

// ---------------- Wo on HMMA: y = fp16(cat) @ fp16(Wo) + bo + emb; emit fp16(y) ----------------
__global__ void __launch_bounds__(256, 2) wo_mma(const float* __restrict__ bo)
{
    extern __shared__ char sm[];
    const int tid = threadIdx.x, lane = tid & 31, wid = tid >> 5;
    const int wm = (wid & 1) * 64, wn = (wid >> 1) * 32;
    const int m0 = blockIdx.x * 128;
    const int n0 = blockIdx.y * 128;

    float acc[4][4][4];
    hmma_loop(g_A2 + (size_t)m0 * KB_DIM, g_Bwo + (size_t)n0 * KB_DIM,
              sm, acc, tid, lane, wm, wn);

    const int er = lane >> 2;
    const int ec = (lane & 3) * 2;
    #pragma unroll
    for (int mi = 0; mi < 4; mi++) {
        #pragma unroll
        for (int nj = 0; nj < 4; nj++) {
            int col = n0 + wn + nj * 8 + ec;
            float b0v = bo[col], b1v = bo[col + 1];
            int row0 = m0 + wm + mi * 16 + er;
            #pragma unroll
            for (int half = 0; half < 2; half++) {
                int row = row0 + half * 8;
                float2 em = *(const float2*)(g_emb + (size_t)row * EMBED + col);
                float y0 = acc[mi][nj][half * 2]     + b0v + em.x;
                float y1 = acc[mi][nj][half * 2 + 1] + b1v + em.y;
                *(__half2*)(g_A3 + (size_t)row * KB_DIM + col) =
                    __half2(__float2half_rn(y0), __float2half_rn(y1));
            }
        }
    }
}

// ---------------- logits on HMMA (4 warps, 64x64 warp tile): out = fp16(y) @ fp16(Wu) + bu ----------------
// out rows have odd stride (VOCAB) -> scalar stores only.
__global__ void __launch_bounds__(128, 2) wu_mma(const float* __restrict__ bu,
                                                 float* __restrict__ out)
{
    extern __shared__ char sm[];
    const int tid = threadIdx.x, lane = tid & 31, wid = tid >> 5;   // wid 0..3
    const int wm = (wid & 1) * 64, wn = (wid >> 1) * 64;
    const int m0 = blockIdx.x * 128;
    const int n0 = blockIdx.y * 128;

    float acc[4][8][4];
    #pragma unroll
    for (int i = 0; i < 4; i++)
        #pragma unroll
        for (int j = 0; j < 8; j++)
            #pragma unroll
            for (int r = 0; r < 4; r++) acc[i][j][r] = 0.f;

    const __half* Ab = g_A3 + (size_t)m0 * KB_DIM;
    const __half* Bb = g_B2 + (size_t)n0 * KB_DIM;
    const uint32_t sb = smem_u32(sm);
    fill_stage_w4(sb,          Ab, Bb, 0, tid); CP_COMMIT();
    fill_stage_w4(sb + STG_SZ, Ab, Bb, 1, tid); CP_COMMIT();

    for (int kt = 0; kt < NK; kt++) {
        CP_WAIT(1);
        __syncthreads();
        if (kt + 2 < NK)
            fill_stage_w4(sb + ((kt + 2) % 3) * STG_SZ, Ab, Bb, kt + 2, tid);
        CP_COMMIT();
        compute_stage_w4(sb + (kt % 3) * STG_SZ, acc, lane, wm, wn);
    }

    const int er = lane >> 2;
    const int ec = (lane & 3) * 2;
    #pragma unroll
    for (int mi = 0; mi < 4; mi++) {
        #pragma unroll
        for (int nj = 0; nj < 8; nj++) {
            int col = n0 + wn + nj * 8 + ec;
            float b0v = (col < VOCAB)     ? __ldg(bu + col)     : 0.f;
            float b1v = (col + 1 < VOCAB) ? __ldg(bu + col + 1) : 0.f;
            int row = m0 + wm + mi * 16 + er;
            float* p0 = out + (size_t)row * VOCAB + col;
            float* p1 = out + (size_t)(row + 8) * VOCAB + col;
            if (col < VOCAB) {
                p0[0] = acc[mi][nj][0] + b0v;
                p1[0] = acc[mi][nj][2] + b0v;
            }
            if (col + 1 < VOCAB) {
                p0[1] = acc[mi][nj][1] + b1v;
                p1[1] = acc[mi][nj][3] + b1v;
            }
        }
    }
}

// ---------------- launch ----------------
#define MMA_SMEM (3 * STG_SZ)   /* 98304 */

extern "C" void kernel_launch(void* const* d_in, const int* in_sizes, int n_in,
                              void* d_out, int out_size)
{
    const int*   x  = (const int*)  d_in[0];
    const float* E  = (const float*)d_in[1];
    const float* pe = (const float*)d_in[2];
    const float* Wq = (const float*)d_in[3];
    const float* bq = (const float*)d_in[4];
    const float* Wk = (const float*)d_in[5];
    const float* bk = (const float*)d_in[6];
    const float* Wv = (const float*)d_in[7];
    const float* bv = (const float*)d_in[8];
    const float* Wo = (const float*)d_in[9];
    const float* bo = (const float*)d_in[10];
    const float* Wu = (const float*)d_in[11];
    const float* bu = (const float*)d_in[12];
    float* out = (float*)d_out;

    cudaFuncSetAttribute(qkv_mma, cudaFuncAttributeMaxDynamicSharedMemorySize, MMA_SMEM);
    cudaFuncSetAttribute(wo_mma,  cudaFuncAttributeMaxDynamicSharedMemorySize, MMA_SMEM);
    cudaFuncSetAttribute(wu_mma,  cudaFuncAttributeMaxDynamicSharedMemorySize, MMA_SMEM);

    embed_kernel<<<4096, 256>>>(x, E, pe);                              // emb + fp16(emb)
    conv_w_all<<<dim3(32, 32, 4), dim3(32, 8)>>>(Wq, Wk, Wv, Wo);       // weight fp16
    conv_wu_kernel<<<dim3(N_PAD / 32, EMBED / 32), dim3(32, 8)>>>(Wu);

    qkv_mma<<<dim3(32, 24), 256, MMA_SMEM>>>(bq, bk, bv);               // q,k,v

    attn_kernel<<<BATCH * NHEAD, 256>>>();                              // -> fp16(cat) in g_A2

    wo_mma<<<dim3(32, 8), 256, MMA_SMEM>>>(bo);                         // fp16(y) -> g_A3

    wu_mma<<<dim3(32, N_PAD / 128), 128, MMA_SMEM>>>(bu, out);          // logits
}

// round 16
// speedup vs baseline: 1.3889x; 1.1231x over previous
#include <cuda_runtime.h>
#include <cuda_fp16.h>
#include <cstdint>

#define BATCH 64
#define SEQ   64
#define EMBED 1024
#define NHEAD 16
#define HDIM  64
#define VOCAB 50257
#define M_TOT (BATCH*SEQ)   /* 4096 */

#define N_PAD  50304        /* 393*128 */
#define KB_DIM 1024         /* K for all GEMMs (pure fp16 pipeline) */
#define NK     16           /* KB_DIM / 64 */

// ---------------- scratch (no allocation allowed) ----------------
__device__ float g_emb[M_TOT*EMBED];
__device__ float g_q  [M_TOT*EMBED];
__device__ float g_k  [M_TOT*EMBED];
__device__ float g_v  [M_TOT*EMBED];
// fp16 operands (K-major, stride KB_DIM)
__device__ __align__(16) __half g_A2  [(size_t)M_TOT * KB_DIM];   // fp16(emb), then fp16(cat)
__device__ __align__(16) __half g_A3  [(size_t)M_TOT * KB_DIM];   // fp16(y)
__device__ __align__(16) __half g_Bqkv[(size_t)3072  * KB_DIM];   // [Wq|Wk|Wv]
__device__ __align__(16) __half g_Bwo [(size_t)EMBED * KB_DIM];   // Wo
__device__ __align__(16) __half g_B2  [(size_t)N_PAD * KB_DIM];   // Wu

// ---------------- helpers ----------------
__device__ __forceinline__ uint32_t smem_u32(const void* p) {
    uint32_t a;
    asm("{ .reg .u64 t; cvta.to.shared.u64 t, %1; cvt.u32.u64 %0, t; }" : "=r"(a) : "l"(p));
    return a;
}
__device__ __forceinline__ void cp16(uint32_t dst, const void* src) {
    asm volatile("cp.async.cg.shared.global [%0], [%1], 16;" :: "r"(dst), "l"(src) : "memory");
}
#define CP_COMMIT() asm volatile("cp.async.commit_group;" ::: "memory")
#define CP_WAIT(N)  asm volatile("cp.async.wait_group %0;" :: "n"(N) : "memory")

__device__ __forceinline__ void ldm_x4(uint32_t (&r)[4], uint32_t addr) {
    asm volatile("ldmatrix.sync.aligned.m8n8.x4.shared.b16 {%0,%1,%2,%3}, [%4];"
        : "=r"(r[0]), "=r"(r[1]), "=r"(r[2]), "=r"(r[3]) : "r"(addr));
}
__device__ __forceinline__ void mma_f16(float (&d)[4], const uint32_t (&a)[4],
                                        uint32_t b0, uint32_t b1) {
    asm volatile("mma.sync.aligned.m16n8k16.row.col.f32.f16.f16.f32 "
        "{%0,%1,%2,%3}, {%4,%5,%6,%7}, {%8,%9}, {%0,%1,%2,%3};"
        : "+f"(d[0]), "+f"(d[1]), "+f"(d[2]), "+f"(d[3])
        : "r"(a[0]), "r"(a[1]), "r"(a[2]), "r"(a[3]), "r"(b0), "r"(b1));
}

// ================= 128x128 HMMA mainloop, 8 warps (qkv / wo) =================
// k-chunk 64 per stage, 3-stage cp.async ring, 2 CTAs/SM.
// Stage layout (32KB): A [2 sub][128 rows][32 fp16 (64B, XOR swizzled)], B same at +16KB.
#define STG_SZ 32768

__device__ __forceinline__ void fill_stage(uint32_t sbase, const __half* Ab,
                                           const __half* Bb, int kt, int tid)
{
    const int ka = kt * 64;
    #pragma unroll
    for (int i = 0; i < 4; i++) {
        int c = tid + i * 256;                 // 0..1023
        int row = c >> 3, ck = c & 7;
        uint32_t off = (ck >> 2) * 8192 + row * 64 + (((ck & 3) ^ ((row >> 1) & 3)) << 4);
        cp16(sbase + off, Ab + (size_t)row * KB_DIM + ka + ck * 8);
    }
    #pragma unroll
    for (int i = 0; i < 4; i++) {
        int c = tid + i * 256;
        int row = c >> 3, ck = c & 7;
        uint32_t off = 16384 + (ck >> 2) * 8192 + row * 64 + (((ck & 3) ^ ((row >> 1) & 3)) << 4);
        cp16(sbase + off, Bb + (size_t)row * KB_DIM + ka + ck * 8);
    }
}

__device__ __forceinline__ void compute_stage(uint32_t sbase, float (&acc)[4][4][4],
                                              int lane, int wm, int wn)
{
    const int a_r8 = (lane & 7) + ((lane >> 3) & 1) * 8;
    const int a_kh = (lane >> 4) * 8;
    const int b_r8 = (lane & 7) + (lane >> 4) * 8;
    const int b_kh = ((lane >> 3) & 1) * 8;
    #pragma unroll
    for (int sub = 0; sub < 2; sub++) {
        const uint32_t A0 = sbase + sub * 8192;
        const uint32_t B0 = sbase + 16384 + sub * 8192;
        #pragma unroll
        for (int ks = 0; ks < 32; ks += 16) {
            uint32_t af[4][4], bf[4][2];
            #pragma unroll
            for (int mi = 0; mi < 4; mi++) {
                int row = wm + mi * 16 + a_r8;
                int kk  = ks + a_kh;
                ldm_x4(af[mi], A0 + row * 64 + (((kk >> 3) ^ ((row >> 1) & 3)) << 4));
            }
            #pragma unroll
            for (int nj = 0; nj < 2; nj++) {
                int row = wn + nj * 16 + b_r8;
                int kk  = ks + b_kh;
                uint32_t t[4];
                ldm_x4(t, B0 + row * 64 + (((kk >> 3) ^ ((row >> 1) & 3)) << 4));
                bf[nj * 2][0]     = t[0]; bf[nj * 2][1]     = t[1];
                bf[nj * 2 + 1][0] = t[2]; bf[nj * 2 + 1][1] = t[3];
            }
            #pragma unroll
            for (int mi = 0; mi < 4; mi++)
                #pragma unroll
                for (int nj = 0; nj < 4; nj++)
                    mma_f16(acc[mi][nj], af[mi], bf[nj][0], bf[nj][1]);
        }
    }
}

__device__ __forceinline__ void hmma_loop(const __half* Ab, const __half* Bb,
                                          char* sm, float (&acc)[4][4][4],
                                          int tid, int lane, int wm, int wn)
{
    #pragma unroll
    for (int i = 0; i < 4; i++)
        #pragma unroll
        for (int j = 0; j < 4; j++)
            #pragma unroll
            for (int r = 0; r < 4; r++) acc[i][j][r] = 0.f;

    const uint32_t sb = smem_u32(sm);
    fill_stage(sb,          Ab, Bb, 0, tid); CP_COMMIT();
    fill_stage(sb + STG_SZ, Ab, Bb, 1, tid); CP_COMMIT();

    for (int kt = 0; kt < NK; kt++) {
        CP_WAIT(1);                 // in-order completion: group kt is done
        __syncthreads();            // data visible; also guards ring reuse (WAR)
        if (kt + 2 < NK)
            fill_stage(sb + ((kt + 2) % 3) * STG_SZ, Ab, Bb, kt + 2, tid);
        CP_COMMIT();                // keep one group per iter (empty ok)
        compute_stage(sb + (kt % 3) * STG_SZ, acc, lane, wm, wn);
    }
}

// ================= 128x128 HMMA mainloop, 4 warps / warp tile 64x64 (wu) =================
__device__ __forceinline__ void fill_stage_w4(uint32_t sbase, const __half* Ab,
                                              const __half* Bb, int kt, int tid)
{
    const int ka = kt * 64;
    #pragma unroll
    for (int i = 0; i < 8; i++) {
        int c = tid + i * 128;                 // 0..1023
        int row = c >> 3, ck = c & 7;
        uint32_t off = (ck >> 2) * 8192 + row * 64 + (((ck & 3) ^ ((row >> 1) & 3)) << 4);
        cp16(sbase + off, Ab + (size_t)row * KB_DIM + ka + ck * 8);
    }
    #pragma unroll
    for (int i = 0; i < 8; i++) {
        int c = tid + i * 128;
        int row = c >> 3, ck = c & 7;
        uint32_t off = 16384 + (ck >> 2) * 8192 + row * 64 + (((ck & 3) ^ ((row >> 1) & 3)) << 4);
        cp16(sbase + off, Bb + (size_t)row * KB_DIM + ka + ck * 8);
    }
}

__device__ __forceinline__ void compute_stage_w4(uint32_t sbase, float (&acc)[4][8][4],
                                                 int lane, int wm, int wn)
{
    const int a_r8 = (lane & 7) + ((lane >> 3) & 1) * 8;
    const int a_kh = (lane >> 4) * 8;
    const int b_r8 = (lane & 7) + (lane >> 4) * 8;
    const int b_kh = ((lane >> 3) & 1) * 8;
    #pragma unroll
    for (int sub = 0; sub < 2; sub++) {
        const uint32_t A0 = sbase + sub * 8192;
        const uint32_t B0 = sbase + 16384 + sub * 8192;
        #pragma unroll
        for (int ks = 0; ks < 32; ks += 16) {
            uint32_t af[4][4], bf[8][2];
            #pragma unroll
            for (int mi = 0; mi < 4; mi++) {
                int row = wm + mi * 16 + a_r8;
                int kk  = ks + a_kh;
                ldm_x4(af[mi], A0 + row * 64 + (((kk >> 3) ^ ((row >> 1) & 3)) << 4));
            }
            #pragma unroll
            for (int njj = 0; njj < 4; njj++) {
                int row = wn + njj * 16 + b_r8;
                int kk  = ks + b_kh;
                uint32_t t[4];
                ldm_x4(t, B0 + row * 64 + (((kk >> 3) ^ ((row >> 1) & 3)) << 4));
                bf[njj * 2][0]     = t[0]; bf[njj * 2][1]     = t[1];
                bf[njj * 2 + 1][0] = t[2]; bf[njj * 2 + 1][1] = t[3];
            }
            #pragma unroll
            for (int mi = 0; mi < 4; mi++)
                #pragma unroll
                for (int nj = 0; nj < 8; nj++)
                    mma_f16(acc[mi][nj], af[mi], bf[nj][0], bf[nj][1]);
        }
    }
}

// ---------------- embed (+ fused fp16 convert into g_A2) ----------------
__global__ void __launch_bounds__(256) embed_kernel(const int* __restrict__ x,
                                                    const float* __restrict__ E,
                                                    const float* __restrict__ pe)
{
    int idx = blockIdx.x * 256 + threadIdx.x;
    int row = idx >> 8;
    int c   = (idx & 255) << 2;
    int tok = x[row];
    float4 e = *(const float4*)(E  + (size_t)tok * EMBED + c);
    float4 p = *(const float4*)(pe + (size_t)(row & 63) * EMBED + c);
    e.x += p.x; e.y += p.y; e.z += p.z; e.w += p.w;
    *(float4*)(g_emb + (size_t)row * EMBED + c) = e;

    size_t base = (size_t)row * KB_DIM + c;
    *(__half2*)(g_A2 + base)     = __half2(__float2half_rn(e.x), __float2half_rn(e.y));
    *(__half2*)(g_A2 + base + 2) = __half2(__float2half_rn(e.z), __float2half_rn(e.w));
}

// ---------------- weight prepass (all four weights, one launch) ----------------
__global__ void __launch_bounds__(256) conv_w_all(const float* __restrict__ Wq,
                                                  const float* __restrict__ Wk,
                                                  const float* __restrict__ Wv,
                                                  const float* __restrict__ Wo)
{
    __shared__ float t[32][33];
    int z  = blockIdx.z;
    int n0 = blockIdx.x * 32;
    int k0 = blockIdx.y * 32;
    int tx = threadIdx.x, ty = threadIdx.y;   // 32 x 8
    if (z < 3) {
        const float* W = (z == 0) ? Wq : (z == 1) ? Wk : Wv;
        int h = n0 >> 6, e0 = n0 & 63;
        #pragma unroll
        for (int i = 0; i < 4; i++) {
            int kk = ty + i * 8;
            t[kk][tx] = W[(size_t)h * (EMBED * HDIM) + (size_t)(k0 + kk) * HDIM + e0 + tx];
        }
        __syncthreads();
        #pragma unroll
        for (int i = 0; i < 4; i++) {
            int nn = ty + i * 8;
            g_Bqkv[(size_t)(z * 1024 + n0 + nn) * KB_DIM + k0 + tx] =
                __float2half_rn(t[tx][nn]);
        }
    } else {
        #pragma unroll
        for (int i = 0; i < 4; i++) {
            int kk = ty + i * 8;
            t[kk][tx] = Wo[(size_t)(k0 + kk) * EMBED + n0 + tx];
        }
        __syncthreads();
        #pragma unroll
        for (int i = 0; i < 4; i++) {
            int nn = ty + i * 8;
            g_Bwo[(size_t)(n0 + nn) * KB_DIM + k0 + tx] = __float2half_rn(t[tx][nn]);
        }
    }
}

// Wu: [1024 k][VOCAB n] (odd stride -> scalar loads) -> g_B2[n][k]
// 64k x 32n tile; stores paired into __half2 for 128B/warp transactions.
__global__ void __launch_bounds__(256) conv_wu_kernel(const float* __restrict__ Wu)
{
    __shared__ float t[64][33];
    int n0 = blockIdx.x * 32;
    int k0 = blockIdx.y * 64;
    int tx = threadIdx.x, ty = threadIdx.y;   // 32 x 8
    #pragma unroll
    for (int i = 0; i < 8; i++) {
        int k = k0 + ty + i * 8;
        int n = n0 + tx;
        t[ty + i * 8][tx] = (n < VOCAB) ? Wu[(size_t)k * VOCAB + n] : 0.f;
    }
    __syncthreads();
    #pragma unroll
    for (int i = 0; i < 4; i++) {
        int n  = n0 + ty + i * 8;
        int nn = ty + i * 8;
        int kk = tx * 2;
        __half2 v(__float2half_rn(t[kk][nn]), __float2half_rn(t[kk + 1][nn]));
        *(__half2*)(g_B2 + (size_t)n * KB_DIM + k0 + kk) = v;
    }
}

// ---------------- attention (fp32) + fused fp16 cat into g_A2 ----------------
__global__ void __launch_bounds__(256) attn_kernel()
{
    __shared__ float sQ [64][68];
    __shared__ float sKV[64][68];
    int bh  = blockIdx.x;
    int tid = threadIdx.x;
    const float* qb = g_q + (size_t)bh * (SEQ * HDIM);
    const float* kb = g_k + (size_t)bh * (SEQ * HDIM);
    const float* vb = g_v + (size_t)bh * (SEQ * HDIM);
    #pragma unroll
    for (int i = 0; i < 4; i++) {
        int idx = tid + i * 256;
        int r = idx >> 4, c = (idx & 15) << 2;
        *(float4*)(&sQ [r][c]) = *(const float4*)(qb + r * 64 + c);
        *(float4*)(&sKV[r][c]) = *(const float4*)(kb + r * 64 + c);
    }
    __syncthreads();

    int s = tid >> 2, q = tid & 3;
    float4 qv[16];
    #pragma unroll
    for (int k4 = 0; k4 < 16; k4++) qv[k4] = *(const float4*)(&sQ[s][k4 * 4]);

    float sc[16];
    #pragma unroll
    for (int j = 0; j < 16; j++) {
        int t = q + 4 * j;
        float d = 0.f;
        #pragma unroll
        for (int k4 = 0; k4 < 16; k4++) {
            float4 kv = *(const float4*)(&sKV[t][k4 * 4]);
            d += qv[k4].x * kv.x + qv[k4].y * kv.y + qv[k4].z * kv.z + qv[k4].w * kv.w;
        }
        sc[j] = (t <= s) ? d * 0.125f : -1e30f;
    }
    float mx = sc[0];
    #pragma unroll
    for (int j = 1; j < 16; j++) mx = fmaxf(mx, sc[j]);
    mx = fmaxf(mx, __shfl_xor_sync(0xFFFFFFFFu, mx, 1));
    mx = fmaxf(mx, __shfl_xor_sync(0xFFFFFFFFu, mx, 2));
    float sum = 0.f;
    #pragma unroll
    for (int j = 0; j < 16; j++) { sc[j] = __expf(sc[j] - mx); sum += sc[j]; }
    sum += __shfl_xor_sync(0xFFFFFFFFu, sum, 1);
    sum += __shfl_xor_sync(0xFFFFFFFFu, sum, 2);
    float inv = 1.f / sum;
    #pragma unroll
    for (int j = 0; j < 16; j++) sc[j] *= inv;

    __syncthreads();
    #pragma unroll
    for (int i = 0; i < 4; i++) {
        int idx = tid + i * 256;
        int r = idx >> 4, c = (idx & 15) << 2;
        *(float4*)(&sKV[r][c]) = *(const float4*)(vb + r * 64 + c);
    }
    __syncthreads();

    float po[64];
    #pragma unroll
    for (int e = 0; e < 64; e++) po[e] = 0.f;
    #pragma unroll
    for (int j = 0; j < 16; j++) {
        int t = q + 4 * j;
        float w = sc[j];
        #pragma unroll
        for (int e4 = 0; e4 < 16; e4++) {
            float4 v = *(const float4*)(&sKV[t][e4 * 4]);
            po[e4 * 4 + 0] += w * v.x;
            po[e4 * 4 + 1] += w * v.y;
            po[e4 * 4 + 2] += w * v.z;
            po[e4 * 4 + 3] += w * v.w;
        }
    }
    #pragma unroll
    for (int e = 0; e < 64; e++) {
        po[e] += __shfl_xor_sync(0xFFFFFFFFu, po[e], 1);
        po[e] += __shfl_xor_sync(0xFFFFFFFFu, po[e], 2);
    }
    // fused fp16 cat: this thread owns row (b,s), cols h*64 + [16q, 16q+16)
    int b = bh >> 4, h = bh & 15;
    int row = b * SEQ + s;
    size_t base = (size_t)row * KB_DIM + h * HDIM + q * 16;
    #pragma unroll
    for (int i = 0; i < 8; i++) {
        int e0 = q * 16 + i * 2;
        *(__half2*)(g_A2 + base + i * 2) =
            __half2(__float2half_rn(po[e0]), __float2half_rn(po[e0 + 1]));
    }
}

// ---------------- QKV on HMMA: fp16(emb) @ fp16([Wq|Wk|Wv]) ----------------
__global__ void __launch_bounds__(256, 2) qkv_mma(const float* __restrict__ bq,
                                                  const float* __restrict__ bk,
                                                  const float* __restrict__ bv)
{
    extern __shared__ char sm[];
    const int tid = threadIdx.x, lane = tid & 31, wid = tid >> 5;
    const int wm = (wid & 1) * 64, wn = (wid >> 1) * 32;
    const int m0 = blockIdx.x * 128;
    const int n0 = blockIdx.y * 128;     // global n in [0, 3072)

    float acc[4][4][4];
    hmma_loop(g_A2 + (size_t)m0 * KB_DIM, g_Bqkv + (size_t)n0 * KB_DIM,
              sm, acc, tid, lane, wm, wn);

    const int which = n0 >> 10;          // uniform per CTA
    float* outp = (which == 0) ? g_q : (which == 1) ? g_k : g_v;
    const float* bias = (which == 0) ? bq : (which == 1) ? bk : bv;

    const int er = lane >> 2;
    const int ec = (lane & 3) * 2;
    #pragma unroll
    for (int mi = 0; mi < 4; mi++) {
        #pragma unroll
        for (int nj = 0; nj < 4; nj++) {
            int col = n0 + wn + nj * 8 + ec;      // global
            int n   = col & 1023;                  // within weight
            int h = n >> 6, e = n & 63;
            float b0v = bias[n], b1v = bias[n + 1];
            int row0 = m0 + wm + mi * 16 + er;
            #pragma unroll
            for (int half = 0; half < 2; half++) {
                int row = row0 + half * 8;
                int b = row >> 6, s = row & 63;
                float* dst = outp + (size_t)(((b * NHEAD + h) * SEQ + s) * HDIM + e);
                *(float2*)dst = make_float2(acc[mi][nj][half * 2] + b0v,
                                            acc[mi][nj][half * 2 + 1] + b1v);
            }
        }
    }
}

// ---------------- Wo on HMMA: y = fp16(cat) @ fp16(Wo) + bo + emb; emit fp16(y) ----------------
__global__ void __launch_bounds__(256, 2) wo_mma(const float* __restrict__ bo)
{
    extern __shared__ char sm[];
    const int tid = threadIdx.x, lane = tid & 31, wid = tid >> 5;
    const int wm = (wid & 1) * 64, wn = (wid >> 1) * 32;
    const int m0 = blockIdx.x * 128;
    const int n0 = blockIdx.y * 128;

    float acc[4][4][4];
    hmma_loop(g_A2 + (size_t)m0 * KB_DIM, g_Bwo + (size_t)n0 * KB_DIM,
              sm, acc, tid, lane, wm, wn);

    const int er = lane >> 2;
    const int ec = (lane & 3) * 2;
    #pragma unroll
    for (int mi = 0; mi < 4; mi++) {
        #pragma unroll
        for (int nj = 0; nj < 4; nj++) {
            int col = n0 + wn + nj * 8 + ec;
            float b0v = bo[col], b1v = bo[col + 1];
            int row0 = m0 + wm + mi * 16 + er;
            #pragma unroll
            for (int half = 0; half < 2; half++) {
                int row = row0 + half * 8;
                float2 em = *(const float2*)(g_emb + (size_t)row * EMBED + col);
                float y0 = acc[mi][nj][half * 2]     + b0v + em.x;
                float y1 = acc[mi][nj][half * 2 + 1] + b1v + em.y;
                *(__half2*)(g_A3 + (size_t)row * KB_DIM + col) =
                    __half2(__float2half_rn(y0), __float2half_rn(y1));
            }
        }
    }
}

// ---------------- logits on HMMA (4 warps, 64x64 warp tile): out = fp16(y) @ fp16(Wu) + bu ----------------
// Epilogue stages the 128x128 tile through smem (reusing the dead ring buffer)
// so global stores are fully coalesced 32-lane rows. Scalar STG.32 only
// (out rows have odd stride VOCAB).
#define EPI_PITCH 136

__global__ void __launch_bounds__(128, 2) wu_mma(const float* __restrict__ bu,
                                                 float* __restrict__ out)
{
    extern __shared__ char sm[];
    const int tid = threadIdx.x, lane = tid & 31, wid = tid >> 5;   // wid 0..3
    const int wm = (wid & 1) * 64, wn = (wid >> 1) * 64;
    const int m0 = blockIdx.x * 128;
    const int n0 = blockIdx.y * 128;

    float acc[4][8][4];
    #pragma unroll
    for (int i = 0; i < 4; i++)
        #pragma unroll
        for (int j = 0; j < 8; j++)
            #pragma unroll
            for (int r = 0; r < 4; r++) acc[i][j][r] = 0.f;

    const __half* Ab = g_A3 + (size_t)m0 * KB_DIM;
    const __half* Bb = g_B2 + (size_t)n0 * KB_DIM;
    const uint32_t sb = smem_u32(sm);
    fill_stage_w4(sb,          Ab, Bb, 0, tid); CP_COMMIT();
    fill_stage_w4(sb + STG_SZ, Ab, Bb, 1, tid); CP_COMMIT();

    for (int kt = 0; kt < NK; kt++) {
        CP_WAIT(1);
        __syncthreads();
        if (kt + 2 < NK)
            fill_stage_w4(sb + ((kt + 2) % 3) * STG_SZ, Ab, Bb, kt + 2, tid);
        CP_COMMIT();
        compute_stage_w4(sb + (kt % 3) * STG_SZ, acc, lane, wm, wn);
    }

    // --- epilogue: stage in smem, then coalesced row writes ---
    __syncthreads();                       // ring buffer dead; all compute done
    float* stg = (float*)sm;               // 128 x EPI_PITCH fp32 = 69.6KB (< 96KB)
    const int er = lane >> 2;
    const int ec = (lane & 3) * 2;
    #pragma unroll
    for (int mi = 0; mi < 4; mi++) {
        #pragma unroll
        for (int nj = 0; nj < 8; nj++) {
            int r = wm + mi * 16 + er;
            int c = wn + nj * 8 + ec;
            stg[r * EPI_PITCH + c]           = acc[mi][nj][0];
            stg[r * EPI_PITCH + c + 1]       = acc[mi][nj][1];
            stg[(r + 8) * EPI_PITCH + c]     = acc[mi][nj][2];
            stg[(r + 8) * EPI_PITCH + c + 1] = acc[mi][nj][3];
        }
    }
    __syncthreads();
    for (int r = wid; r < 128; r += 4) {
        size_t rowoff = (size_t)(m0 + r) * VOCAB;
        const float* srow = stg + r * EPI_PITCH;
        #pragma unroll
        for (int i = 0; i < 4; i++) {
            int c = i * 32 + lane;
            int col = n0 + c;
            if (col < VOCAB)
                out[rowoff + col] = srow[c] + __ldg(bu + col);
        }
    }
}

// ---------------- launch ----------------
#define MMA_SMEM (3 * STG_SZ)   /* 98304 */

extern "C" void kernel_launch(void* const* d_in, const int* in_sizes, int n_in,
                              void* d_out, int out_size)
{
    const int*   x  = (const int*)  d_in[0];
    const float* E  = (const float*)d_in[1];
    const float* pe = (const float*)d_in[2];
    const float* Wq = (const float*)d_in[3];
    const float* bq = (const float*)d_in[4];
    const float* Wk = (const float*)d_in[5];
    const float* bk = (const float*)d_in[6];
    const float* Wv = (const float*)d_in[7];
    const float* bv = (const float*)d_in[8];
    const float* Wo = (const float*)d_in[9];
    const float* bo = (const float*)d_in[10];
    const float* Wu = (const float*)d_in[11];
    const float* bu = (const float*)d_in[12];
    float* out = (float*)d_out;

    cudaFuncSetAttribute(qkv_mma, cudaFuncAttributeMaxDynamicSharedMemorySize, MMA_SMEM);
    cudaFuncSetAttribute(wo_mma,  cudaFuncAttributeMaxDynamicSharedMemorySize, MMA_SMEM);
    cudaFuncSetAttribute(wu_mma,  cudaFuncAttributeMaxDynamicSharedMemorySize, MMA_SMEM);

    embed_kernel<<<4096, 256>>>(x, E, pe);                              // emb + fp16(emb)
    conv_w_all<<<dim3(32, 32, 4), dim3(32, 8)>>>(Wq, Wk, Wv, Wo);       // weight fp16
    conv_wu_kernel<<<dim3(N_PAD / 32, EMBED / 64), dim3(32, 8)>>>(Wu);

    qkv_mma<<<dim3(32, 24), 256, MMA_SMEM>>>(bq, bk, bv);               // q,k,v

    attn_kernel<<<BATCH * NHEAD, 256>>>();                              // -> fp16(cat) in g_A2

    wo_mma<<<dim3(32, 8), 256, MMA_SMEM>>>(bo);                         // fp16(y) -> g_A3

    wu_mma<<<dim3(32, N_PAD / 128), 128, MMA_SMEM>>>(bu, out);          // logits
}

// round 17
// speedup vs baseline: 1.4288x; 1.0287x over previous
#include <cuda_runtime.h>
#include <cuda_fp16.h>
#include <cstdint>

#define BATCH 64
#define SEQ   64
#define EMBED 1024
#define NHEAD 16
#define HDIM  64
#define VOCAB 50257
#define M_TOT (BATCH*SEQ)   /* 4096 */

#define N_PAD  50304        /* 393*128 */
#define KB_DIM 1024         /* K for all GEMMs (pure fp16 pipeline) */
#define NK     16           /* KB_DIM / 64 */

// ---------------- scratch (no allocation allowed) ----------------
__device__ float g_emb[M_TOT*EMBED];
__device__ float g_q  [M_TOT*EMBED];
__device__ float g_k  [M_TOT*EMBED];
__device__ float g_v  [M_TOT*EMBED];
// fp16 operands (K-major, stride KB_DIM)
__device__ __align__(16) __half g_A2  [(size_t)M_TOT * KB_DIM];   // fp16(emb), then fp16(cat)
__device__ __align__(16) __half g_A3  [(size_t)M_TOT * KB_DIM];   // fp16(y)
__device__ __align__(16) __half g_Bqkv[(size_t)3072  * KB_DIM];   // [Wq|Wk|Wv]
__device__ __align__(16) __half g_Bwo [(size_t)EMBED * KB_DIM];   // Wo
__device__ __align__(16) __half g_B2  [(size_t)N_PAD * KB_DIM];   // Wu

// ---------------- helpers ----------------
__device__ __forceinline__ uint32_t smem_u32(const void* p) {
    uint32_t a;
    asm("{ .reg .u64 t; cvta.to.shared.u64 t, %1; cvt.u32.u64 %0, t; }" : "=r"(a) : "l"(p));
    return a;
}
__device__ __forceinline__ void cp16(uint32_t dst, const void* src) {
    asm volatile("cp.async.cg.shared.global [%0], [%1], 16;" :: "r"(dst), "l"(src) : "memory");
}
#define CP_COMMIT() asm volatile("cp.async.commit_group;" ::: "memory")
#define CP_WAIT(N)  asm volatile("cp.async.wait_group %0;" :: "n"(N) : "memory")

__device__ __forceinline__ void ldm_x4(uint32_t (&r)[4], uint32_t addr) {
    asm volatile("ldmatrix.sync.aligned.m8n8.x4.shared.b16 {%0,%1,%2,%3}, [%4];"
        : "=r"(r[0]), "=r"(r[1]), "=r"(r[2]), "=r"(r[3]) : "r"(addr));
}
__device__ __forceinline__ void mma_f16(float (&d)[4], const uint32_t (&a)[4],
                                        uint32_t b0, uint32_t b1) {
    asm volatile("mma.sync.aligned.m16n8k16.row.col.f32.f16.f16.f32 "
        "{%0,%1,%2,%3}, {%4,%5,%6,%7}, {%8,%9}, {%0,%1,%2,%3};"
        : "+f"(d[0]), "+f"(d[1]), "+f"(d[2]), "+f"(d[3])
        : "r"(a[0]), "r"(a[1]), "r"(a[2]), "r"(a[3]), "r"(b0), "r"(b1));
}

// ================= shared 128x128 HMMA mainloop: 4 warps, warp tile 64x64 =================
// k-chunk 64 per stage, 3-stage cp.async ring, 2 CTAs/SM (128 thr -> 256-reg budget).
// Stage layout (32KB): A [2 sub][128 rows][32 fp16 (64B, XOR swizzled)], B same at +16KB.
// Fragments are double-buffered in registers: next (sub,ks) ldmatrix overlaps current mma.
#define STG_SZ 32768

__device__ __forceinline__ void fill_stage_w4(uint32_t sbase, const __half* Ab,
                                              const __half* Bb, int kt, int tid)
{
    const int ka = kt * 64;
    #pragma unroll
    for (int i = 0; i < 8; i++) {
        int c = tid + i * 128;                 // 0..1023
        int row = c >> 3, ck = c & 7;
        uint32_t off = (ck >> 2) * 8192 + row * 64 + (((ck & 3) ^ ((row >> 1) & 3)) << 4);
        cp16(sbase + off, Ab + (size_t)row * KB_DIM + ka + ck * 8);
    }
    #pragma unroll
    for (int i = 0; i < 8; i++) {
        int c = tid + i * 128;
        int row = c >> 3, ck = c & 7;
        uint32_t off = 16384 + (ck >> 2) * 8192 + row * 64 + (((ck & 3) ^ ((row >> 1) & 3)) << 4);
        cp16(sbase + off, Bb + (size_t)row * KB_DIM + ka + ck * 8);
    }
}

struct Frag { uint32_t af[4][4]; uint32_t bf[8][2]; };

// it in 0..3: sub = it>>1, ks = (it&1)*16
__device__ __forceinline__ void load_frags(Frag& f, uint32_t sbase, int it,
                                           int lane, int wm, int wn)
{
    const int a_r8 = (lane & 7) + ((lane >> 3) & 1) * 8;
    const int a_kh = (lane >> 4) * 8;
    const int b_r8 = (lane & 7) + (lane >> 4) * 8;
    const int b_kh = ((lane >> 3) & 1) * 8;
    const int sub = it >> 1;
    const int ks  = (it & 1) * 16;
    const uint32_t A0 = sbase + sub * 8192;
    const uint32_t B0 = sbase + 16384 + sub * 8192;
    #pragma unroll
    for (int mi = 0; mi < 4; mi++) {
        int row = wm + mi * 16 + a_r8;
        int kk  = ks + a_kh;
        ldm_x4(f.af[mi], A0 + row * 64 + (((kk >> 3) ^ ((row >> 1) & 3)) << 4));
    }
    #pragma unroll
    for (int njj = 0; njj < 4; njj++) {
        int row = wn + njj * 16 + b_r8;
        int kk  = ks + b_kh;
        uint32_t t[4];
        ldm_x4(t, B0 + row * 64 + (((kk >> 3) ^ ((row >> 1) & 3)) << 4));
        f.bf[njj * 2][0]     = t[0]; f.bf[njj * 2][1]     = t[1];
        f.bf[njj * 2 + 1][0] = t[2]; f.bf[njj * 2 + 1][1] = t[3];
    }
}

__device__ __forceinline__ void mma_frags(float (&acc)[4][8][4], const Frag& f)
{
    #pragma unroll
    for (int mi = 0; mi < 4; mi++)
        #pragma unroll
        for (int nj = 0; nj < 8; nj++)
            mma_f16(acc[mi][nj], f.af[mi], f.bf[nj][0], f.bf[nj][1]);
}

__device__ __forceinline__ void hmma_loop_w4(const __half* Ab, const __half* Bb,
                                             char* sm, float (&acc)[4][8][4],
                                             int tid, int lane, int wm, int wn)
{
    #pragma unroll
    for (int i = 0; i < 4; i++)
        #pragma unroll
        for (int j = 0; j < 8; j++)
            #pragma unroll
            for (int r = 0; r < 4; r++) acc[i][j][r] = 0.f;

    const uint32_t sb = smem_u32(sm);
    fill_stage_w4(sb,          Ab, Bb, 0, tid); CP_COMMIT();
    fill_stage_w4(sb + STG_SZ, Ab, Bb, 1, tid); CP_COMMIT();

    Frag f[2];
    for (int kt = 0; kt < NK; kt++) {
        CP_WAIT(1);
        __syncthreads();
        if (kt + 2 < NK)
            fill_stage_w4(sb + ((kt + 2) % 3) * STG_SZ, Ab, Bb, kt + 2, tid);
        CP_COMMIT();
        const uint32_t cs = sb + (kt % 3) * STG_SZ;
        load_frags(f[0], cs, 0, lane, wm, wn);
        #pragma unroll
        for (int it = 0; it < 4; it++) {
            if (it < 3) load_frags(f[(it + 1) & 1], cs, it + 1, lane, wm, wn);
            mma_frags(acc, f[it & 1]);
        }
    }
}

// ---------------- embed (+ fused fp16 convert into g_A2) ----------------
__global__ void __launch_bounds__(256) embed_kernel(const int* __restrict__ x,
                                                    const float* __restrict__ E,
                                                    const float* __restrict__ pe)
{
    int idx = blockIdx.x * 256 + threadIdx.x;
    int row = idx >> 8;
    int c   = (idx & 255) << 2;
    int tok = x[row];
    float4 e = *(const float4*)(E  + (size_t)tok * EMBED + c);
    float4 p = *(const float4*)(pe + (size_t)(row & 63) * EMBED + c);
    e.x += p.x; e.y += p.y; e.z += p.z; e.w += p.w;
    *(float4*)(g_emb + (size_t)row * EMBED + c) = e;

    size_t base = (size_t)row * KB_DIM + c;
    *(__half2*)(g_A2 + base)     = __half2(__float2half_rn(e.x), __float2half_rn(e.y));
    *(__half2*)(g_A2 + base + 2) = __half2(__float2half_rn(e.z), __float2half_rn(e.w));
}

// ---------------- weight prepass (all four weights, one launch) ----------------
__global__ void __launch_bounds__(256) conv_w_all(const float* __restrict__ Wq,
                                                  const float* __restrict__ Wk,
                                                  const float* __restrict__ Wv,
                                                  const float* __restrict__ Wo)
{
    __shared__ float t[32][33];
    int z  = blockIdx.z;
    int n0 = blockIdx.x * 32;
    int k0 = blockIdx.y * 32;
    int tx = threadIdx.x, ty = threadIdx.y;   // 32 x 8
    if (z < 3) {
        const float* W = (z == 0) ? Wq : (z == 1) ? Wk : Wv;
        int h = n0 >> 6, e0 = n0 & 63;
        #pragma unroll
        for (int i = 0; i < 4; i++) {
            int kk = ty + i * 8;
            t[kk][tx] = W[(size_t)h * (EMBED * HDIM) + (size_t)(k0 + kk) * HDIM + e0 + tx];
        }
        __syncthreads();
        #pragma unroll
        for (int i = 0; i < 4; i++) {
            int nn = ty + i * 8;
            g_Bqkv[(size_t)(z * 1024 + n0 + nn) * KB_DIM + k0 + tx] =
                __float2half_rn(t[tx][nn]);
        }
    } else {
        #pragma unroll
        for (int i = 0; i < 4; i++) {
            int kk = ty + i * 8;
            t[kk][tx] = Wo[(size_t)(k0 + kk) * EMBED + n0 + tx];
        }
        __syncthreads();
        #pragma unroll
        for (int i = 0; i < 4; i++) {
            int nn = ty + i * 8;
            g_Bwo[(size_t)(n0 + nn) * KB_DIM + k0 + tx] = __float2half_rn(t[tx][nn]);
        }
    }
}

// Wu: [1024 k][VOCAB n] (odd stride -> scalar loads) -> g_B2[n][k]
// 64k x 32n tile; stores paired into __half2 for 128B/warp transactions.
__global__ void __launch_bounds__(256) conv_wu_kernel(const float* __restrict__ Wu)
{
    __shared__ float t[64][33];
    int n0 = blockIdx.x * 32;
    int k0 = blockIdx.y * 64;
    int tx = threadIdx.x, ty = threadIdx.y;   // 32 x 8
    #pragma unroll
    for (int i = 0; i < 8; i++) {
        int k = k0 + ty + i * 8;
        int n = n0 + tx;
        t[ty + i * 8][tx] = (n < VOCAB) ? Wu[(size_t)k * VOCAB + n] : 0.f;
    }
    __syncthreads();
    #pragma unroll
    for (int i = 0; i < 4; i++) {
        int n  = n0 + ty + i * 8;
        int nn = ty + i * 8;
        int kk = tx * 2;
        __half2 v(__float2half_rn(t[kk][nn]), __float2half_rn(t[kk + 1][nn]));
        *(__half2*)(g_B2 + (size_t)n * KB_DIM + k0 + kk) = v;
    }
}

// ---------------- attention (fp32) + fused fp16 cat into g_A2 ----------------
__global__ void __launch_bounds__(256) attn_kernel()
{
    __shared__ float sQ [64][68];
    __shared__ float sKV[64][68];
    int bh  = blockIdx.x;
    int tid = threadIdx.x;
    const float* qb = g_q + (size_t)bh * (SEQ * HDIM);
    const float* kb = g_k + (size_t)bh * (SEQ * HDIM);
    const float* vb = g_v + (size_t)bh * (SEQ * HDIM);
    #pragma unroll
    for (int i = 0; i < 4; i++) {
        int idx = tid + i * 256;
        int r = idx >> 4, c = (idx & 15) << 2;
        *(float4*)(&sQ [r][c]) = *(const float4*)(qb + r * 64 + c);
        *(float4*)(&sKV[r][c]) = *(const float4*)(kb + r * 64 + c);
    }
    __syncthreads();

    int s = tid >> 2, q = tid & 3;
    float4 qv[16];
    #pragma unroll
    for (int k4 = 0; k4 < 16; k4++) qv[k4] = *(const float4*)(&sQ[s][k4 * 4]);

    float sc[16];
    #pragma unroll
    for (int j = 0; j < 16; j++) {
        int t = q + 4 * j;
        float d = 0.f;
        #pragma unroll
        for (int k4 = 0; k4 < 16; k4++) {
            float4 kv = *(const float4*)(&sKV[t][k4 * 4]);
            d += qv[k4].x * kv.x + qv[k4].y * kv.y + qv[k4].z * kv.z + qv[k4].w * kv.w;
        }
        sc[j] = (t <= s) ? d * 0.125f : -1e30f;
    }
    float mx = sc[0];
    #pragma unroll
    for (int j = 1; j < 16; j++) mx = fmaxf(mx, sc[j]);
    mx = fmaxf(mx, __shfl_xor_sync(0xFFFFFFFFu, mx, 1));
    mx = fmaxf(mx, __shfl_xor_sync(0xFFFFFFFFu, mx, 2));
    float sum = 0.f;
    #pragma unroll
    for (int j = 0; j < 16; j++) { sc[j] = __expf(sc[j] - mx); sum += sc[j]; }
    sum += __shfl_xor_sync(0xFFFFFFFFu, sum, 1);
    sum += __shfl_xor_sync(0xFFFFFFFFu, sum, 2);
    float inv = 1.f / sum;
    #pragma unroll
    for (int j = 0; j < 16; j++) sc[j] *= inv;

    __syncthreads();
    #pragma unroll
    for (int i = 0; i < 4; i++) {
        int idx = tid + i * 256;
        int r = idx >> 4, c = (idx & 15) << 2;
        *(float4*)(&sKV[r][c]) = *(const float4*)(vb + r * 64 + c);
    }
    __syncthreads();

    float po[64];
    #pragma unroll
    for (int e = 0; e < 64; e++) po[e] = 0.f;
    #pragma unroll
    for (int j = 0; j < 16; j++) {
        int t = q + 4 * j;
        float w = sc[j];
        #pragma unroll
        for (int e4 = 0; e4 < 16; e4++) {
            float4 v = *(const float4*)(&sKV[t][e4 * 4]);
            po[e4 * 4 + 0] += w * v.x;
            po[e4 * 4 + 1] += w * v.y;
            po[e4 * 4 + 2] += w * v.z;
            po[e4 * 4 + 3] += w * v.w;
        }
    }
    #pragma unroll
    for (int e = 0; e < 64; e++) {
        po[e] += __shfl_xor_sync(0xFFFFFFFFu, po[e], 1);
        po[e] += __shfl_xor_sync(0xFFFFFFFFu, po[e], 2);
    }
    // fused fp16 cat: this thread owns row (b,s), cols h*64 + [16q, 16q+16)
    int b = bh >> 4, h = bh & 15;
    int row = b * SEQ + s;
    size_t base = (size_t)row * KB_DIM + h * HDIM + q * 16;
    #pragma unroll
    for (int i = 0; i < 8; i++) {
        int e0 = q * 16 + i * 2;
        *(__half2*)(g_A2 + base + i * 2) =
            __half2(__float2half_rn(po[e0]), __float2half_rn(po[e0 + 1]));
    }
}

// ---------------- QKV on HMMA (4 warps): fp16(emb) @ fp16([Wq|Wk|Wv]) ----------------
__global__ void __launch_bounds__(128, 2) qkv_mma(const float* __restrict__ bq,
                                                  const float* __restrict__ bk,
                                                  const float* __restrict__ bv)
{
    extern __shared__ char sm[];
    const int tid = threadIdx.x, lane = tid & 31, wid = tid >> 5;
    const int wm = (wid & 1) * 64, wn = (wid >> 1) * 64;
    const int m0 = blockIdx.x * 128;
    const int n0 = blockIdx.y * 128;     // global n in [0, 3072)

    float acc[4][8][4];
    hmma_loop_w4(g_A2 + (size_t)m0 * KB_DIM, g_Bqkv + (size_t)n0 * KB_DIM,
                 sm, acc, tid, lane, wm, wn);

    const int which = n0 >> 10;          // uniform per CTA
    float* outp = (which == 0) ? g_q : (which == 1) ? g_k : g_v;
    const float* bias = (which == 0) ? bq : (which == 1) ? bk : bv;

    const int er = lane >> 2;
    const int ec = (lane & 3) * 2;
    #pragma unroll
    for (int mi = 0; mi < 4; mi++) {
        #pragma unroll
        for (int nj = 0; nj < 8; nj++) {
            int col = n0 + wn + nj * 8 + ec;      // global
            int n   = col & 1023;                  // within weight
            int h = n >> 6, e = n & 63;
            float b0v = bias[n], b1v = bias[n + 1];
            int row0 = m0 + wm + mi * 16 + er;
            #pragma unroll
            for (int half = 0; half < 2; half++) {
                int row = row0 + half * 8;
                int b = row >> 6, s = row & 63;
                float* dst = outp + (size_t)(((b * NHEAD + h) * SEQ + s) * HDIM + e);
                *(float2*)dst = make_float2(acc[mi][nj][half * 2] + b0v,
                                            acc[mi][nj][half * 2 + 1] + b1v);
            }
        }
    }
}

// ---------------- Wo on HMMA (4 warps): y = fp16(cat) @ fp16(Wo) + bo + emb; emit fp16(y) ----------------
__global__ void __launch_bounds__(128, 2) wo_mma(const float* __restrict__ bo)
{
    extern __shared__ char sm[];
    const int tid = threadIdx.x, lane = tid & 31, wid = tid >> 5;
    const int wm = (wid & 1) * 64, wn = (wid >> 1) * 64;
    const int m0 = blockIdx.x * 128;
    const int n0 = blockIdx.y * 128;

    float acc[4][8][4];
    hmma_loop_w4(g_A2 + (size_t)m0 * KB_DIM, g_Bwo + (size_t)n0 * KB_DIM,
                 sm, acc, tid, lane, wm, wn);

    const int er = lane >> 2;
    const int ec = (lane & 3) * 2;
    #pragma unroll
    for (int mi = 0; mi < 4; mi++) {
        #pragma unroll
        for (int nj = 0; nj < 8; nj++) {
            int col = n0 + wn + nj * 8 + ec;
            float b0v = bo[col], b1v = bo[col + 1];
            int row0 = m0 + wm + mi * 16 + er;
            #pragma unroll
            for (int half = 0; half < 2; half++) {
                int row = row0 + half * 8;
                float2 em = *(const float2*)(g_emb + (size_t)row * EMBED + col);
                float y0 = acc[mi][nj][half * 2]     + b0v + em.x;
                float y1 = acc[mi][nj][half * 2 + 1] + b1v + em.y;
                *(__half2*)(g_A3 + (size_t)row * KB_DIM + col) =
                    __half2(__float2half_rn(y0), __float2half_rn(y1));
            }
        }
    }
}

// ---------------- logits on HMMA (4 warps): out = fp16(y) @ fp16(Wu) + bu ----------------
// Epilogue stages the 128x128 tile through smem (dead ring buffer) so global
// stores are fully coalesced rows. Scalar STG.32 only (odd row stride VOCAB).
#define EPI_PITCH 136

__global__ void __launch_bounds__(128, 2) wu_mma(const float* __restrict__ bu,
                                                 float* __restrict__ out)
{
    extern __shared__ char sm[];
    const int tid = threadIdx.x, lane = tid & 31, wid = tid >> 5;   // wid 0..3
    const int wm = (wid & 1) * 64, wn = (wid >> 1) * 64;
    const int m0 = blockIdx.x * 128;
    const int n0 = blockIdx.y * 128;

    float acc[4][8][4];
    hmma_loop_w4(g_A3 + (size_t)m0 * KB_DIM, g_B2 + (size_t)n0 * KB_DIM,
                 sm, acc, tid, lane, wm, wn);

    // --- epilogue: stage in smem, then coalesced row writes ---
    __syncthreads();                       // ring buffer dead; all compute done
    float* stg = (float*)sm;               // 128 x EPI_PITCH fp32 = 69.6KB (< 96KB)
    const int er = lane >> 2;
    const int ec = (lane & 3) * 2;
    #pragma unroll
    for (int mi = 0; mi < 4; mi++) {
        #pragma unroll
        for (int nj = 0; nj < 8; nj++) {
            int r = wm + mi * 16 + er;
            int c = wn + nj * 8 + ec;
            stg[r * EPI_PITCH + c]           = acc[mi][nj][0];
            stg[r * EPI_PITCH + c + 1]       = acc[mi][nj][1];
            stg[(r + 8) * EPI_PITCH + c]     = acc[mi][nj][2];
            stg[(r + 8) * EPI_PITCH + c + 1] = acc[mi][nj][3];
        }
    }
    __syncthreads();
    for (int r = wid; r < 128; r += 4) {
        size_t rowoff = (size_t)(m0 + r) * VOCAB;
        const float* srow = stg + r * EPI_PITCH;
        #pragma unroll
        for (int i = 0; i < 4; i++) {
            int c = i * 32 + lane;
            int col = n0 + c;
            if (col < VOCAB)
                out[rowoff + col] = srow[c] + __ldg(bu + col);
        }
    }
}

// ---------------- launch ----------------
#define MMA_SMEM (3 * STG_SZ)   /* 98304 */

extern "C" void kernel_launch(void* const* d_in, const int* in_sizes, int n_in,
                              void* d_out, int out_size)
{
    const int*   x  = (const int*)  d_in[0];
    const float* E  = (const float*)d_in[1];
    const float* pe = (const float*)d_in[2];
    const float* Wq = (const float*)d_in[3];
    const float* bq = (const float*)d_in[4];
    const float* Wk = (const float*)d_in[5];
    const float* bk = (const float*)d_in[6];
    const float* Wv = (const float*)d_in[7];
    const float* bv = (const float*)d_in[8];
    const float* Wo = (const float*)d_in[9];
    const float* bo = (const float*)d_in[10];
    const float* Wu = (const float*)d_in[11];
    const float* bu = (const float*)d_in[12];
    float* out = (float*)d_out;

    cudaFuncSetAttribute(qkv_mma, cudaFuncAttributeMaxDynamicSharedMemorySize, MMA_SMEM);
    cudaFuncSetAttribute(wo_mma,  cudaFuncAttributeMaxDynamicSharedMemorySize, MMA_SMEM);
    cudaFuncSetAttribute(wu_mma,  cudaFuncAttributeMaxDynamicSharedMemorySize, MMA_SMEM);

    embed_kernel<<<4096, 256>>>(x, E, pe);                              // emb + fp16(emb)
    conv_w_all<<<dim3(32, 32, 4), dim3(32, 8)>>>(Wq, Wk, Wv, Wo);       // weight fp16
    conv_wu_kernel<<<dim3(N_PAD / 32, EMBED / 64), dim3(32, 8)>>>(Wu);

    qkv_mma<<<dim3(32, 24), 128, MMA_SMEM>>>(bq, bk, bv);               // q,k,v

    attn_kernel<<<BATCH * NHEAD, 256>>>();                              // -> fp16(cat) in g_A2

    wo_mma<<<dim3(32, 8), 128, MMA_SMEM>>>(bo);                         // fp16(y) -> g_A3

    wu_mma<<<dim3(32, N_PAD / 128), 128, MMA_SMEM>>>(bu, out);          // logits
}